// round 14
// baseline (speedup 1.0000x reference)
#include <cuda_runtime.h>
#include <cuda_bf16.h>
#include <math.h>
#include <stdint.h>

// Problem constants (fixed by setup_inputs)
#define BB    4
#define TT    1024
#define CC    768
#define HH    12
#define DH    64
#define BT    4096            // B*T
#define C3    2304            // 3*C
#define C4    3072            // 4*C
#define ZSZ   3145728         // BT*C
#define NUM_ITERS 6
// pair (bf16x2) leading dims
#define CCP   384
#define C3P   1152
#define C4P   1536
#define TTP   512
#define DHP   32

#define LOG2E 1.4426950408889634f
#define SEXP  0.18033688011112042f    // 0.125 * log2(e)

// ---------------- scratch (device globals; no allocation allowed) -----------
__device__ float g_z[ZSZ];
__device__ float g_zattn[ZSZ];
__device__ float g_res[ZSZ];
__device__ float g_fhist[4 * ZSZ];

// hi/lo bf16x2 planes (pairs packed along k)
__device__ uint32_t g_x_h[BT * CCP],    g_x_l[BT * CCP];
__device__ uint32_t g_qkv_h[BT * C3P],  g_qkv_l[BT * C3P];
__device__ uint32_t g_vt_h[BB * HH * DH * TTP], g_vt_l[BB * HH * DH * TTP];
__device__ uint32_t g_ao_h[BT * CCP],   g_ao_l[BT * CCP];
__device__ uint32_t g_mid_h[BT * C4P],  g_mid_l[BT * C4P];
// weight planes (split once per launch)
__device__ uint32_t g_wqkv_h[C3 * CCP], g_wqkv_l[C3 * CCP];
__device__ uint32_t g_wo_h[CC * CCP],   g_wo_l[CC * CCP];
__device__ uint32_t g_w1_h[C4 * CCP],   g_w1_l[C4 * CCP];
__device__ uint32_t g_w2_h[CC * C4P],   g_w2_l[CC * C4P];

// ---------------- helpers ------------------------------------------------------
__device__ __forceinline__ void split2(float x, float y, uint32_t& hi, uint32_t& lo) {
    __nv_bfloat162 h2 = __floats2bfloat162_rn(x, y);
    float lx = x - __low2float(h2);
    float ly = y - __high2float(h2);
    __nv_bfloat162 l2 = __floats2bfloat162_rn(lx, ly);
    hi = *reinterpret_cast<uint32_t*>(&h2);
    lo = *reinterpret_cast<uint32_t*>(&l2);
}

__device__ __forceinline__ void mma16(float c[4], const uint32_t a[4], const uint32_t b[2]) {
    asm volatile(
        "mma.sync.aligned.m16n8k16.row.col.f32.bf16.bf16.f32 "
        "{%0,%1,%2,%3}, {%4,%5,%6,%7}, {%8,%9}, {%0,%1,%2,%3};\n"
        : "+f"(c[0]), "+f"(c[1]), "+f"(c[2]), "+f"(c[3])
        : "r"(a[0]), "r"(a[1]), "r"(a[2]), "r"(a[3]), "r"(b[0]), "r"(b[1]));
}

__device__ __forceinline__ void ldm4(uint32_t r[4], uint32_t addr) {
    asm volatile("ldmatrix.sync.aligned.m8n8.x4.shared.b16 {%0,%1,%2,%3}, [%4];"
        : "=r"(r[0]), "=r"(r[1]), "=r"(r[2]), "=r"(r[3]) : "r"(addr));
}

__device__ __forceinline__ uint32_t smem_u32(const void* p) {
    return (uint32_t)__cvta_generic_to_shared(p);
}

__device__ __forceinline__ void cp16(uint32_t dst, const uint32_t* src) {
    asm volatile("cp.async.cg.shared.global [%0], [%1], 16;" :: "r"(dst), "l"(src));
}
#define CP_COMMIT() asm volatile("cp.async.commit_group;" ::: "memory")
#define CP_WAIT0()  asm volatile("cp.async.wait_group 0;" ::: "memory")
#define CP_WAIT1()  asm volatile("cp.async.wait_group 1;" ::: "memory")

// ---------------- weight/activation split kernel ------------------------------
__global__ void conv_kernel(const float* __restrict__ w,
                            uint32_t* __restrict__ h,
                            uint32_t* __restrict__ l, int npairs) {
    int i = blockIdx.x * 256 + threadIdx.x;
    if (i < npairs) {
        float2 x = ((const float2*)w)[i];
        uint32_t hv, lv;
        split2(x.x, x.y, hv, lv);
        h[i] = hv; l[i] = lv;
    }
}

// ---------------- flash attention (fused QK^T + softmax + AV) ------------------
// grid (TT/128, BB*HH), block 256 = 8 warps; warp w owns q-rows [w*16, w*16+16).
// K-loop: 16 tiles of 64 tokens; K and V^T both streamed via cp.async (2 stages).
// SMEM (words): stage s @ s*9216: Kh 0 | Kl 2304 | Vh 4608 | Vl 6912.
//               P/Q: Ph @18432, Pl @23040. Total 27648 words = 110592 B.
__global__ void __launch_bounds__(256) flash_attn(
    const uint32_t* __restrict__ qh_g, const uint32_t* __restrict__ ql_g,
    const uint32_t* __restrict__ vth,  const uint32_t* __restrict__ vtl,
    uint32_t* __restrict__ aoh, uint32_t* __restrict__ aol)
{
    extern __shared__ __align__(16) uint32_t dsm[];
    const int tid = threadIdx.x, lane = tid & 31, w = tid >> 5;
    const int bh = blockIdx.y, b = bh / HH, h = bh % HH;
    const int m0 = blockIdx.x * 128;
    const long tokb = (long)b * TT;
    const int hq = h * DHP;
    const int hk = CCP + h * DHP;
    const size_t vtb = (size_t)bh * DH * TTP;
    const uint32_t smb = smem_u32(dsm);
    const int qr = lane >> 2, kp = lane & 3;

    // ---- stage Q into P region and load register fragments ----
    for (int i = 0; i < 4; i++) {
        const int idx = tid + i * 256;            // 0..1023
        const int row = idx >> 3, ch = idx & 7;
        const size_t src = (size_t)(tokb + m0 + row) * C3P + hq + ch * 4;
        *(uint4*)&dsm[18432 + row * 36 + ch * 4] = *(const uint4*)(qh_g + src);
        *(uint4*)&dsm[23040 + row * 36 + ch * 4] = *(const uint4*)(ql_g + src);
    }
    __syncthreads();
    uint32_t qfh[4][4], qfl[4][4];
    {
        const uint32_t ao = smb + (uint32_t)(w * 16 + (lane & 15)) * 144 +
                            (uint32_t)(lane >> 4) * 16;
        for (int j = 0; j < 4; j++) {
            ldm4(qfh[j], ao + 18432 * 4 + j * 32);
            ldm4(qfl[j], ao + 23040 * 4 + j * 32);
        }
    }
    __syncthreads();                               // P region now reusable

    // ---- K + V^T prefetch via cp.async ----
    auto issueK = [&](int kt) {
        const uint32_t stb = smb + (uint32_t)(kt & 1) * (9216 * 4);
        for (int i = 0; i < 2; i++) {
            const int idx = tid + i * 256;         // 0..511
            const int row = idx >> 3, ch = idx & 7;
            const size_t ksrc = (size_t)(tokb + kt * 64 + row) * C3P + hk + ch * 4;
            const uint32_t kdst = stb + (uint32_t)row * 144 + (uint32_t)ch * 16;
            cp16(kdst, qh_g + ksrc);
            cp16(kdst + 2304 * 4, ql_g + ksrc);
            const size_t vsrc = vtb + (size_t)row * TTP + kt * 32 + ch * 4;
            const uint32_t vdst = kdst + 4608 * 4;
            cp16(vdst, vth + vsrc);
            cp16(vdst + 2304 * 4, vtl + vsrc);
        }
        CP_COMMIT();
    };
    issueK(0);

    float O[8][4];
#pragma unroll
    for (int nt = 0; nt < 8; nt++)
#pragma unroll
        for (int e = 0; e < 4; e++) O[nt][e] = 0.0f;
    float m0r = -1e30f, m1r = -1e30f, l0 = 0.0f, l1 = 0.0f;

    const uint32_t bof = (uint32_t)(((lane >> 4) & 1) * 8 + (lane & 7)) * 144 +
                         (uint32_t)((lane >> 3) & 1) * 16;
    const uint32_t aof = smb + (uint32_t)(w * 16 + (lane & 15)) * 144 +
                         (uint32_t)(lane >> 4) * 16;

    for (int kt = 0; kt < 16; kt++) {
        CP_WAIT0();
        __syncthreads();                           // K/V[kt] ready, prev AV done
        if (kt + 1 < 16) issueK(kt + 1);

        // ---- S = Q K^T (raw, scale folded into exp) ----
        float sacc[8][4];
#pragma unroll
        for (int nt = 0; nt < 8; nt++)
#pragma unroll
            for (int e = 0; e < 4; e++) sacc[nt][e] = 0.0f;
        const uint32_t stb = smb + (uint32_t)(kt & 1) * (9216 * 4);
#pragma unroll
        for (int g = 0; g < 4; g++)
#pragma unroll
            for (int j = 0; j < 4; j++) {
                uint32_t kb[4], kl[4];
                ldm4(kb, stb + bof + g * (16 * 144) + j * 32);
                ldm4(kl, stb + 2304 * 4 + bof + g * (16 * 144) + j * 32);
#pragma unroll
                for (int t = 0; t < 2; t++) {
                    const int nt = 2 * g + t;
                    mma16(sacc[nt], qfh[j], &kl[2 * t]);
                    mma16(sacc[nt], qfl[j], &kb[2 * t]);
                    mma16(sacc[nt], qfh[j], &kb[2 * t]);
                }
            }

        // ---- online softmax (rows qr / qr+8 of this warp's 16-row block) ----
        float tm0 = -1e30f, tm1 = -1e30f;
#pragma unroll
        for (int nt = 0; nt < 8; nt++) {
            tm0 = fmaxf(tm0, fmaxf(sacc[nt][0], sacc[nt][1]));
            tm1 = fmaxf(tm1, fmaxf(sacc[nt][2], sacc[nt][3]));
        }
        tm0 = fmaxf(tm0, __shfl_xor_sync(0xffffffff, tm0, 1));
        tm0 = fmaxf(tm0, __shfl_xor_sync(0xffffffff, tm0, 2));
        tm1 = fmaxf(tm1, __shfl_xor_sync(0xffffffff, tm1, 1));
        tm1 = fmaxf(tm1, __shfl_xor_sync(0xffffffff, tm1, 2));
        const float mn0 = fmaxf(m0r, tm0 * 0.125f);
        const float mn1 = fmaxf(m1r, tm1 * 0.125f);
        const float f0 = exp2f((m0r - mn0) * LOG2E);
        const float f1 = exp2f((m1r - mn1) * LOG2E);
        m0r = mn0; m1r = mn1;
        const float mm0 = mn0 * LOG2E, mm1 = mn1 * LOG2E;
        float s0 = 0.0f, s1 = 0.0f;
        const int pr0 = (w * 16 + qr) * 36 + kp;
        const int pr1 = pr0 + 8 * 36;
#pragma unroll
        for (int nt = 0; nt < 8; nt++) {
            const float p0 = exp2f(fmaf(sacc[nt][0], SEXP, -mm0));
            const float p1 = exp2f(fmaf(sacc[nt][1], SEXP, -mm0));
            const float p2 = exp2f(fmaf(sacc[nt][2], SEXP, -mm1));
            const float p3 = exp2f(fmaf(sacc[nt][3], SEXP, -mm1));
            s0 += p0 + p1; s1 += p2 + p3;
            uint32_t hh, ll;
            split2(p0, p1, hh, ll);
            dsm[18432 + pr0 + nt * 4] = hh;
            dsm[23040 + pr0 + nt * 4] = ll;
            split2(p2, p3, hh, ll);
            dsm[18432 + pr1 + nt * 4] = hh;
            dsm[23040 + pr1 + nt * 4] = ll;
        }
        s0 += __shfl_xor_sync(0xffffffff, s0, 1);
        s0 += __shfl_xor_sync(0xffffffff, s0, 2);
        s1 += __shfl_xor_sync(0xffffffff, s1, 1);
        s1 += __shfl_xor_sync(0xffffffff, s1, 2);
        l0 = l0 * f0 + s0;
        l1 = l1 * f1 + s1;
#pragma unroll
        for (int nt = 0; nt < 8; nt++) {
            O[nt][0] *= f0; O[nt][1] *= f0;
            O[nt][2] *= f1; O[nt][3] *= f1;
        }
        __syncthreads();                           // P visible

        // ---- O += P V ----
#pragma unroll
        for (int j = 0; j < 4; j++) {
            uint32_t pah[4], pal[4];
            ldm4(pah, aof + 18432 * 4 + j * 32);
            ldm4(pal, aof + 23040 * 4 + j * 32);
#pragma unroll
            for (int g = 0; g < 4; g++) {
                uint32_t vbh[4], vbl[4];
                ldm4(vbh, stb + 4608 * 4 + bof + g * (16 * 144) + j * 32);
                ldm4(vbl, stb + 6912 * 4 + bof + g * (16 * 144) + j * 32);
#pragma unroll
                for (int t = 0; t < 2; t++) {
                    const int nt = 2 * g + t;
                    mma16(O[nt], pah, &vbl[2 * t]);
                    mma16(O[nt], pal, &vbh[2 * t]);
                    mma16(O[nt], pah, &vbh[2 * t]);
                }
            }
        }
    }

    // ---- epilogue: O /= l, write attention-out planes ----
    const float il0 = 1.0f / l0, il1 = 1.0f / l1;
    const size_t r0g = (size_t)(tokb + m0 + w * 16 + qr) * CCP + hq + kp;
    const size_t r1g = r0g + (size_t)8 * CCP;
#pragma unroll
    for (int nt = 0; nt < 8; nt++) {
        uint32_t hh, ll;
        split2(O[nt][0] * il0, O[nt][1] * il0, hh, ll);
        aoh[r0g + nt * 4] = hh; aol[r0g + nt * 4] = ll;
        split2(O[nt][2] * il1, O[nt][3] * il1, hh, ll);
        aoh[r1g + nt * 4] = hh; aol[r1g + nt * 4] = ll;
    }
}

// ---------------- unified tensor-core GEMM (bf16x3, cp.async 3-stage) ---------
// out[m,n] = sum_k A[m,k] * B[n,k]   (planes pre-split, pairs packed along k).
// Tile: 128(M) x 64(N) x 16(K), 8 warps (4x2), warp tile 32x32.
// MODE: 0 +bias | 1 gelu(+bias) | 2 +bias+add1 | 3 +bias+add1-add2
// VOUT: tiles with n0 >= 2*CC write V^T planes (token-paired) instead.
template<int MODE, bool OUTP, bool VOUT>
__global__ void __launch_bounds__(256, 3) mma_gemm(
    const uint32_t* __restrict__ Agh, const uint32_t* __restrict__ Agl,
    const uint32_t* __restrict__ Bgh, const uint32_t* __restrict__ Bgl,
    const float* __restrict__ bias,
    float* __restrict__ outF, uint32_t* __restrict__ outH, uint32_t* __restrict__ outL,
    uint32_t* __restrict__ vth, uint32_t* __restrict__ vtl,
    int K, int ldaP, int ldbP, int ldc,
    const float* __restrict__ add1, const float* __restrict__ add2)
{
    extern __shared__ __align__(16) uint32_t dsm[];
    constexpr uint32_t STB     = 18432;      // bytes/stage
    constexpr uint32_t OFF_AL  = 6144;
    constexpr uint32_t OFF_BH  = 12288;
    constexpr uint32_t OFF_BL  = 15360;

    const int tid  = threadIdx.x;
    const int lane = tid & 31;
    const int wid  = tid >> 5;
    const int wm   = wid >> 1;
    const int wn   = wid & 1;
    const int m0   = blockIdx.y * 128;
    const int n0   = blockIdx.x * 64;

    const int nsteps = K >> 4;

    const int arow = tid >> 1;
    const int akq  = (tid & 1) << 2;

    const uint32_t smb = smem_u32(dsm);
    const uint32_t aoff = (uint32_t)(wm * 32 + (lane & 15)) * 48 + (uint32_t)(lane >> 4) * 16;
    const uint32_t boff = (uint32_t)(wn * 32 + ((lane >> 4) & 1) * 8 + (lane & 7)) * 48 +
                          (uint32_t)((lane >> 3) & 1) * 16;

    auto issue = [&](int s, int st) {
        const uint32_t stb = smb + (uint32_t)st * STB;
        const size_t aog = (size_t)(m0 + arow) * ldaP + (s << 3) + akq;
        const uint32_t adst = stb + (uint32_t)arow * 48 + (uint32_t)akq * 4;
        cp16(adst, Agh + aog);
        cp16(adst + OFF_AL, Agl + aog);
        if (tid < 128) {
            const int br = tid >> 1;
            const size_t bog = (size_t)(n0 + br) * ldbP + (s << 3) + akq;
            const uint32_t bdst = stb + OFF_BH + (uint32_t)br * 48 + (uint32_t)akq * 4;
            cp16(bdst, Bgh + bog);
            cp16(bdst + (OFF_BL - OFF_BH), Bgl + bog);
        }
    };

    // prologue: stages 0,1
    issue(0, 0); CP_COMMIT();
    if (1 < nsteps) issue(1, 1);
    CP_COMMIT();

    float acc[2][4][4];
#pragma unroll
    for (int i = 0; i < 2; i++)
#pragma unroll
        for (int j = 0; j < 4; j++)
#pragma unroll
            for (int e = 0; e < 4; e++) acc[i][j][e] = 0.0f;

    const int kp = lane & 3;
    const int qr = lane >> 2;

    int st = 0, stn = 2;          // current stage, next-issue stage (mod 3)
    for (int s = 0; s < nsteps; s++) {
        CP_WAIT1();
        __syncthreads();
        if (s + 2 < nsteps) issue(s + 2, stn);
        CP_COMMIT();

        const uint32_t stb = smb + (uint32_t)st * STB;
        uint32_t ah[2][4], al4[2][4];
#pragma unroll
        for (int mt = 0; mt < 2; mt++) {
            const uint32_t ao = aoff + (uint32_t)mt * 768;
            ldm4(ah[mt],  stb + ao);
            ldm4(al4[mt], stb + OFF_AL + ao);
        }
        uint32_t bfh[2][4], bfl[2][4];
#pragma unroll
        for (int ntp = 0; ntp < 2; ntp++) {
            const uint32_t bo = boff + (uint32_t)ntp * 768;
            ldm4(bfh[ntp], stb + OFF_BH + bo);
            ldm4(bfl[ntp], stb + OFF_BL + bo);
        }
#pragma unroll
        for (int mt = 0; mt < 2; mt++)
#pragma unroll
            for (int ntp = 0; ntp < 2; ntp++)
#pragma unroll
                for (int j = 0; j < 2; j++) {
                    const int nt = 2 * ntp + j;
                    mma16(acc[mt][nt], ah[mt],  &bfl[ntp][2 * j]);
                    mma16(acc[mt][nt], al4[mt], &bfh[ntp][2 * j]);
                    mma16(acc[mt][nt], ah[mt],  &bfh[ntp][2 * j]);
                }

        st = (st == 2) ? 0 : st + 1;
        stn = (stn == 2) ? 0 : stn + 1;
    }

    // ---- epilogue ------------------------------------------------------------
    const bool vtile = VOUT && (n0 >= 2 * CC);
#pragma unroll
    for (int mt = 0; mt < 2; mt++) {
#pragma unroll
        for (int nt = 0; nt < 4; nt++) {
            const int r = m0 + wm * 32 + mt * 16 + qr;
            const int c = n0 + wn * 32 + nt * 8 + 2 * kp;
            float vv[4];
#pragma unroll
            for (int e = 0; e < 4; e++) {
                const int cc = c + (e & 1);
                float v = acc[mt][nt][e];
                v += bias[cc];
                if (MODE == 1) v = 0.5f * v * (1.0f + erff(v * 0.70710678118654752f));
                vv[e] = v;
            }
            if (vtile) {
                // V^T planes: pairs along tokens via lane exchange (qr bit0)
                const float o0 = __shfl_xor_sync(0xffffffff, vv[0], 4);
                const float o1 = __shfl_xor_sync(0xffffffff, vv[1], 4);
                const float o2 = __shfl_xor_sync(0xffffffff, vv[2], 4);
                const float o3 = __shfl_xor_sync(0xffffffff, vv[3], 4);
                const int b = m0 >> 10;
                const int head = (n0 - 2 * CC) >> 6;
                const int t = r - (b << 10);
                const int d = c - n0;
                const size_t base = (size_t)(b * HH + head) * (DH * TTP) +
                                    (size_t)d * TTP;
                uint32_t hh, ll;
                if ((qr & 1) == 0) {
                    const int tp = t >> 1;
                    split2(vv[0], o0, hh, ll);
                    vth[base + tp] = hh;        vtl[base + tp] = ll;
                    split2(vv[1], o1, hh, ll);
                    vth[base + TTP + tp] = hh;  vtl[base + TTP + tp] = ll;
                } else {
                    const int tp = (t + 7) >> 1;      // even token t-1+8
                    split2(o2, vv[2], hh, ll);
                    vth[base + tp] = hh;        vtl[base + tp] = ll;
                    split2(o3, vv[3], hh, ll);
                    vth[base + TTP + tp] = hh;  vtl[base + TTP + tp] = ll;
                }
            } else if (OUTP) {
                const int cp = c >> 1;
                uint32_t h0, l0, h1, l1;
                split2(vv[0], vv[1], h0, l0);
                split2(vv[2], vv[3], h1, l1);
                outH[(size_t)r * ldc + cp] = h0;
                outL[(size_t)r * ldc + cp] = l0;
                outH[(size_t)(r + 8) * ldc + cp] = h1;
                outL[(size_t)(r + 8) * ldc + cp] = l1;
            } else {
#pragma unroll
                for (int e = 0; e < 4; e++) {
                    const int rr = r + (e >> 1) * 8;
                    const int cc = c + (e & 1);
                    const size_t oidx = (size_t)rr * ldc + cc;
                    float v = vv[e];
                    if (MODE == 2) v += add1[oidx];
                    if (MODE == 3) v += add1[oidx] - add2[oidx];
                    outF[oidx] = v;
                }
            }
        }
    }
}

// ---------------- fused add + LayerNorm -> hi/lo planes -----------------------
__global__ void ln_kernel(const float* __restrict__ zin,
                          const float* __restrict__ u,
                          const float* __restrict__ emb,
                          const float* __restrict__ w,
                          const float* __restrict__ b,
                          uint32_t* __restrict__ oh,
                          uint32_t* __restrict__ ol) {
    __shared__ float red[256];
    const int row = blockIdx.x;
    const int tid = threadIdx.x;
    const size_t base = (size_t)row * CC;
    const float2* z2 = (const float2*)(zin + base);
    const float2* u2 = u ? (const float2*)(u + base) : nullptr;
    const float2* e2 = emb ? (const float2*)emb : nullptr;

    float2 va = z2[tid];
    float2 vb = make_float2(0.f, 0.f);
    if (u2) { float2 t = u2[tid]; va.x += t.x; va.y += t.y; }
    if (e2) { float2 t = e2[tid]; va.x += 0.1f * t.x; va.y += 0.1f * t.y; }
    if (tid < 128) {
        vb = z2[256 + tid];
        if (u2) { float2 t = u2[256 + tid]; vb.x += t.x; vb.y += t.y; }
        if (e2) { float2 t = e2[256 + tid]; vb.x += 0.1f * t.x; vb.y += 0.1f * t.y; }
    }
    float s = va.x + va.y + vb.x + vb.y;
    red[tid] = s; __syncthreads();
    for (int st = 128; st > 0; st >>= 1) {
        if (tid < st) red[tid] += red[tid + st];
        __syncthreads();
    }
    const float mu = red[0] * (1.0f / CC);
    __syncthreads();
    va.x -= mu; va.y -= mu;
    float s2 = va.x * va.x + va.y * va.y;
    if (tid < 128) { vb.x -= mu; vb.y -= mu; s2 += vb.x * vb.x + vb.y * vb.y; }
    red[tid] = s2; __syncthreads();
    for (int st = 128; st > 0; st >>= 1) {
        if (tid < st) red[tid] += red[tid + st];
        __syncthreads();
    }
    const float rs = rsqrtf(red[0] * (1.0f / CC) + 1e-5f);

    const float2* w2 = (const float2*)w;
    const float2* b2 = (const float2*)b;
    {
        float2 wc = w2[tid], bc = b2[tid];
        float y0 = va.x * rs * wc.x + bc.x;
        float y1 = va.y * rs * wc.y + bc.y;
        uint32_t hv, lv;
        split2(y0, y1, hv, lv);
        oh[(size_t)row * CCP + tid] = hv;
        ol[(size_t)row * CCP + tid] = lv;
    }
    if (tid < 128) {
        float2 wc = w2[256 + tid], bc = b2[256 + tid];
        float y0 = vb.x * rs * wc.x + bc.x;
        float y1 = vb.y * rs * wc.y + bc.y;
        uint32_t hv, lv;
        split2(y0, y1, hv, lv);
        oh[(size_t)row * CCP + 256 + tid] = hv;
        ol[(size_t)row * CCP + 256 + tid] = lv;
    }
}

// ---------------- fused Anderson update + next-iteration LN1 ------------------
// One block per token. Anderson update of z (identical math to the standalone
// kernel), z_new staged in smem, then LN1(z_new + u + 0.1*emb) -> x planes.
__global__ void anderson_ln_kernel(float* __restrict__ z,
                                   const float* __restrict__ res,
                                   float* __restrict__ fh, int it,
                                   const float* __restrict__ u,
                                   const float* __restrict__ emb,
                                   const float* __restrict__ w,
                                   const float* __restrict__ b,
                                   uint32_t* __restrict__ oh,
                                   uint32_t* __restrict__ ol) {
    __shared__ float sh[14][256];
    __shared__ float alpha_sh[4];
    __shared__ float zrow[CC];
    const int n = blockIdx.x, tid = threadIdx.x;
    const size_t base = (size_t)n * CC;
    const int K = it < 4 ? it : 4;
    const int c0 = tid, c1 = tid + 256, c2 = tid + 512;

    float r0 = res[base + c0], r1 = res[base + c1], r2 = res[base + c2];
    float dF[4][3];
    for (int j = 0; j < K; j++) {
        const int slot = (it - K + j) & 3;
        const float* f = fh + (size_t)slot * ZSZ + base;
        dF[j][0] = f[c0] - r0; dF[j][1] = f[c1] - r1; dF[j][2] = f[c2] - r2;
    }

    float z0 = z[base + c0], z1 = z[base + c1], z2v = z[base + c2];

    if (K > 0) {
        int idx = 0;
        for (int k = 0; k < K; k++)
            for (int l = k; l < K; l++) {
                sh[idx][tid] = dF[k][0] * dF[l][0] + dF[k][1] * dF[l][1] + dF[k][2] * dF[l][2];
                idx++;
            }
        for (int k = 0; k < K; k++) {
            sh[idx][tid] = dF[k][0] * r0 + dF[k][1] * r1 + dF[k][2] * r2;
            idx++;
        }
        const int np = idx;
        __syncthreads();
        for (int st = 128; st > 0; st >>= 1) {
            if (tid < st)
                for (int v = 0; v < np; v++) sh[v][tid] += sh[v][tid + st];
            __syncthreads();
        }
        if (tid == 0) {
            float G[4][4], bv[4], al[4];
            int id2 = 0;
            for (int k = 0; k < K; k++)
                for (int l = k; l < K; l++) { G[k][l] = G[l][k] = sh[id2][0]; id2++; }
            for (int k = 0; k < K; k++) { G[k][k] += 1e-6f; bv[k] = sh[id2][0]; id2++; }
            for (int p = 0; p < K; p++) {
                const float inv = 1.0f / G[p][p];
                for (int rr = p + 1; rr < K; rr++) {
                    const float f2 = G[rr][p] * inv;
                    for (int cc = p; cc < K; cc++) G[rr][cc] -= f2 * G[p][cc];
                    bv[rr] -= f2 * bv[p];
                }
            }
            for (int p = K - 1; p >= 0; p--) {
                float s = bv[p];
                for (int cc = p + 1; cc < K; cc++) s -= G[p][cc] * al[cc];
                al[p] = s / G[p][p];
            }
            for (int k = 0; k < K; k++) alpha_sh[k] = al[k];
        }
        __syncthreads();
        float d0 = r0, d1 = r1, d2 = r2;
        for (int j = 0; j < K; j++) {
            const float a = alpha_sh[j];
            d0 -= a * dF[j][0]; d1 -= a * dF[j][1]; d2 -= a * dF[j][2];
        }
        z0 += d0; z1 += d1; z2v += d2;
    } else {
        z0 += r0; z1 += r1; z2v += r2;
    }

    z[base + c0] = z0; z[base + c1] = z1; z[base + c2] = z2v;
    zrow[c0] = z0; zrow[c1] = z1; zrow[c2] = z2v;

    float* fs = fh + (size_t)(it & 3) * ZSZ + base;
    fs[c0] = r0; fs[c1] = r1; fs[c2] = r2;
    __syncthreads();

    // ---- LN1 of next iteration: LN(zrow + u + 0.1*emb) -> planes -------------
    float* red = sh[0];
    const float2* u2 = (const float2*)(u + base);
    const float2* e2 = (const float2*)emb;
    const float2* zr2 = (const float2*)zrow;

    float2 va = zr2[tid];
    float2 vb = make_float2(0.f, 0.f);
    { float2 t = u2[tid]; va.x += t.x; va.y += t.y; }
    { float2 t = e2[tid]; va.x += 0.1f * t.x; va.y += 0.1f * t.y; }
    if (tid < 128) {
        vb = zr2[256 + tid];
        { float2 t = u2[256 + tid]; vb.x += t.x; vb.y += t.y; }
        { float2 t = e2[256 + tid]; vb.x += 0.1f * t.x; vb.y += 0.1f * t.y; }
    }
    float s = va.x + va.y + vb.x + vb.y;
    red[tid] = s; __syncthreads();
    for (int st = 128; st > 0; st >>= 1) {
        if (tid < st) red[tid] += red[tid + st];
        __syncthreads();
    }
    const float mu = red[0] * (1.0f / CC);
    __syncthreads();
    va.x -= mu; va.y -= mu;
    float s2 = va.x * va.x + va.y * va.y;
    if (tid < 128) { vb.x -= mu; vb.y -= mu; s2 += vb.x * vb.x + vb.y * vb.y; }
    red[tid] = s2; __syncthreads();
    for (int st = 128; st > 0; st >>= 1) {
        if (tid < st) red[tid] += red[tid + st];
        __syncthreads();
    }
    const float rs = rsqrtf(red[0] * (1.0f / CC) + 1e-5f);

    const float2* w2 = (const float2*)w;
    const float2* b2 = (const float2*)b;
    {
        float2 wc = w2[tid], bc = b2[tid];
        float y0 = va.x * rs * wc.x + bc.x;
        float y1 = va.y * rs * wc.y + bc.y;
        uint32_t hv, lv;
        split2(y0, y1, hv, lv);
        oh[(size_t)n * CCP + tid] = hv;
        ol[(size_t)n * CCP + tid] = lv;
    }
    if (tid < 128) {
        float2 wc = w2[256 + tid], bc = b2[256 + tid];
        float y0 = vb.x * rs * wc.x + bc.x;
        float y1 = vb.y * rs * wc.y + bc.y;
        uint32_t hv, lv;
        split2(y0, y1, hv, lv);
        oh[(size_t)n * CCP + 256 + tid] = hv;
        ol[(size_t)n * CCP + 256 + tid] = lv;
    }
}

// ---------------- host launcher ----------------------------------------------
template <typename T>
static T* symaddr(const void* s) {
    void* p = nullptr;
    cudaGetSymbolAddress(&p, s);
    return (T*)p;
}

#define GEMM_SMEM  55296
#define FLASH_SMEM 110592

extern "C" void kernel_launch(void* const* d_in, const int* in_sizes, int n_in,
                              void* d_out, int out_size) {
    const float* u          = (const float*)d_in[0];
    const float* iter_emb   = (const float*)d_in[1];
    const float* ln1_w      = (const float*)d_in[2];
    const float* ln1_b      = (const float*)d_in[3];
    const float* in_proj_w  = (const float*)d_in[4];
    const float* in_proj_b  = (const float*)d_in[5];
    const float* out_proj_w = (const float*)d_in[6];
    const float* out_proj_b = (const float*)d_in[7];
    const float* ln2_w      = (const float*)d_in[8];
    const float* ln2_b      = (const float*)d_in[9];
    const float* mlp_w1     = (const float*)d_in[10];
    const float* mlp_b1     = (const float*)d_in[11];
    const float* mlp_w2     = (const float*)d_in[12];
    const float* mlp_b2     = (const float*)d_in[13];
    // d_in[14] = num_iters (fixed to 6 by setup_inputs)

    float* zp   = symaddr<float>(g_z);
    float* zap  = symaddr<float>(g_zattn);
    float* resp = symaddr<float>(g_res);
    float* fhp  = symaddr<float>(g_fhist);
    uint32_t* xh   = symaddr<uint32_t>(g_x_h);    uint32_t* xl   = symaddr<uint32_t>(g_x_l);
    uint32_t* qh   = symaddr<uint32_t>(g_qkv_h);  uint32_t* ql   = symaddr<uint32_t>(g_qkv_l);
    uint32_t* vth  = symaddr<uint32_t>(g_vt_h);   uint32_t* vtl  = symaddr<uint32_t>(g_vt_l);
    uint32_t* aoh  = symaddr<uint32_t>(g_ao_h);   uint32_t* aol  = symaddr<uint32_t>(g_ao_l);
    uint32_t* mih  = symaddr<uint32_t>(g_mid_h);  uint32_t* mil  = symaddr<uint32_t>(g_mid_l);
    uint32_t* wqh  = symaddr<uint32_t>(g_wqkv_h); uint32_t* wql  = symaddr<uint32_t>(g_wqkv_l);
    uint32_t* woh  = symaddr<uint32_t>(g_wo_h);   uint32_t* wol  = symaddr<uint32_t>(g_wo_l);
    uint32_t* w1h  = symaddr<uint32_t>(g_w1_h);   uint32_t* w1l  = symaddr<uint32_t>(g_w1_l);
    uint32_t* w2h  = symaddr<uint32_t>(g_w2_h);   uint32_t* w2l  = symaddr<uint32_t>(g_w2_l);

    cudaFuncSetAttribute((const void*)mma_gemm<0, true,  true >, cudaFuncAttributeMaxDynamicSharedMemorySize, GEMM_SMEM);
    cudaFuncSetAttribute((const void*)mma_gemm<2, false, false>, cudaFuncAttributeMaxDynamicSharedMemorySize, GEMM_SMEM);
    cudaFuncSetAttribute((const void*)mma_gemm<1, true,  false>, cudaFuncAttributeMaxDynamicSharedMemorySize, GEMM_SMEM);
    cudaFuncSetAttribute((const void*)mma_gemm<3, false, false>, cudaFuncAttributeMaxDynamicSharedMemorySize, GEMM_SMEM);
    cudaFuncSetAttribute((const void*)flash_attn, cudaFuncAttributeMaxDynamicSharedMemorySize, FLASH_SMEM);

    cudaMemsetAsync(zp, 0, (size_t)ZSZ * sizeof(float), 0);

    // split weights once per launch
    conv_kernel<<<(C3 * CCP + 255) / 256, 256>>>(in_proj_w,  wqh, wql, C3 * CCP);
    conv_kernel<<<(CC * CCP + 255) / 256, 256>>>(out_proj_w, woh, wol, CC * CCP);
    conv_kernel<<<(C4 * CCP + 255) / 256, 256>>>(mlp_w1,     w1h, w1l, C4 * CCP);
    conv_kernel<<<(CC * C4P + 255) / 256, 256>>>(mlp_w2,     w2h, w2l, CC * C4P);

    // LN1 for iteration 0 (z = 0)
    ln_kernel<<<BT, 256>>>(zp, u, iter_emb, ln1_w, ln1_b, xh, xl);

    for (int it = 0; it < NUM_ITERS; it++) {
        // qkv = x @ Wqkv^T + b -> Q/K planes; V tiles write V^T planes directly
        mma_gemm<0, true, true><<<dim3(C3 / 64, BT / 128), 256, GEMM_SMEM>>>(
            xh, xl, wqh, wql, in_proj_b, nullptr, qh, ql, vth, vtl,
            CC, CCP, CCP, C3P, nullptr, nullptr);

        // fused attention: softmax(QK^T/8) @ V  -> planes
        flash_attn<<<dim3(TT / 128, BB * HH), 256, FLASH_SMEM>>>(qh, ql, vth, vtl, aoh, aol);

        // z_attn = z + attnout @ Wo^T + bo  (fp32)
        mma_gemm<2, false, false><<<dim3(CC / 64, BT / 128), 256, GEMM_SMEM>>>(
            aoh, aol, woh, wol, out_proj_b, zap, nullptr, nullptr, nullptr, nullptr,
            CC, CCP, CCP, CC, zp, nullptr);

        // h = LN2(z_attn) -> planes
        ln_kernel<<<BT, 256>>>(zap, nullptr, nullptr, ln2_w, ln2_b, xh, xl);

        // mid = gelu(h @ W1^T + b1) -> planes
        mma_gemm<1, true, false><<<dim3(C4 / 64, BT / 128), 256, GEMM_SMEM>>>(
            xh, xl, w1h, w1l, mlp_b1, nullptr, mih, mil, nullptr, nullptr,
            CC, CCP, CCP, C4P, nullptr, nullptr);

        // res = (mid @ W2^T + b2) + z_attn - z  (fp32)
        mma_gemm<3, false, false><<<dim3(CC / 64, BT / 128), 256, GEMM_SMEM>>>(
            mih, mil, w2h, w2l, mlp_b2, resp, nullptr, nullptr, nullptr, nullptr,
            C4, C4P, C4P, CC, zap, zp);

        // Anderson update of z fused with next iteration's LN1 -> x planes
        anderson_ln_kernel<<<BT, 256>>>(zp, resp, fhp, it,
                                        u, iter_emb + (it + 1) * CC,
                                        ln1_w, ln1_b, xh, xl);
    }

    cudaMemcpyAsync(d_out, zp, (size_t)ZSZ * sizeof(float),
                    cudaMemcpyDeviceToDevice, 0);
}

// round 15
// speedup vs baseline: 1.0268x; 1.0268x over previous
#include <cuda_runtime.h>
#include <cuda_bf16.h>
#include <math.h>
#include <stdint.h>

// Problem constants (fixed by setup_inputs)
#define BB    4
#define TT    1024
#define CC    768
#define HH    12
#define DH    64
#define BT    4096            // B*T
#define C3    2304            // 3*C
#define C4    3072            // 4*C
#define ZSZ   3145728         // BT*C
#define NUM_ITERS 6
// pair (bf16x2) leading dims
#define CCP   384
#define C3P   1152
#define C4P   1536
#define TTP   512
#define DHP   32

#define LOG2E 1.4426950408889634f
#define SEXP  0.18033688011112042f    // 0.125 * log2(e)

// ---------------- scratch (device globals; no allocation allowed) -----------
__device__ float g_z[ZSZ];
__device__ float g_zattn[ZSZ];
__device__ float g_res[ZSZ];
__device__ float g_fhist[4 * ZSZ];

// hi/lo bf16x2 planes (pairs packed along k)
__device__ uint32_t g_x_h[BT * CCP],    g_x_l[BT * CCP];
__device__ uint32_t g_qkv_h[BT * C3P],  g_qkv_l[BT * C3P];
__device__ uint32_t g_vt_h[BB * HH * DH * TTP], g_vt_l[BB * HH * DH * TTP];
__device__ uint32_t g_ao_h[BT * CCP],   g_ao_l[BT * CCP];
__device__ uint32_t g_mid_h[BT * C4P],  g_mid_l[BT * C4P];
// weight planes (split once per launch)
__device__ uint32_t g_wqkv_h[C3 * CCP], g_wqkv_l[C3 * CCP];
__device__ uint32_t g_wo_h[CC * CCP],   g_wo_l[CC * CCP];
__device__ uint32_t g_w1_h[C4 * CCP],   g_w1_l[C4 * CCP];
__device__ uint32_t g_w2_h[CC * C4P],   g_w2_l[CC * C4P];

// ---------------- helpers ------------------------------------------------------
__device__ __forceinline__ void split2(float x, float y, uint32_t& hi, uint32_t& lo) {
    __nv_bfloat162 h2 = __floats2bfloat162_rn(x, y);
    float lx = x - __low2float(h2);
    float ly = y - __high2float(h2);
    __nv_bfloat162 l2 = __floats2bfloat162_rn(lx, ly);
    hi = *reinterpret_cast<uint32_t*>(&h2);
    lo = *reinterpret_cast<uint32_t*>(&l2);
}

__device__ __forceinline__ void mma16(float c[4], const uint32_t a[4], const uint32_t b[2]) {
    asm volatile(
        "mma.sync.aligned.m16n8k16.row.col.f32.bf16.bf16.f32 "
        "{%0,%1,%2,%3}, {%4,%5,%6,%7}, {%8,%9}, {%0,%1,%2,%3};\n"
        : "+f"(c[0]), "+f"(c[1]), "+f"(c[2]), "+f"(c[3])
        : "r"(a[0]), "r"(a[1]), "r"(a[2]), "r"(a[3]), "r"(b[0]), "r"(b[1]));
}

__device__ __forceinline__ void ldm4(uint32_t r[4], uint32_t addr) {
    asm volatile("ldmatrix.sync.aligned.m8n8.x4.shared.b16 {%0,%1,%2,%3}, [%4];"
        : "=r"(r[0]), "=r"(r[1]), "=r"(r[2]), "=r"(r[3]) : "r"(addr));
}

__device__ __forceinline__ uint32_t smem_u32(const void* p) {
    return (uint32_t)__cvta_generic_to_shared(p);
}

__device__ __forceinline__ void cp16(uint32_t dst, const uint32_t* src) {
    asm volatile("cp.async.cg.shared.global [%0], [%1], 16;" :: "r"(dst), "l"(src));
}
#define CP_COMMIT() asm volatile("cp.async.commit_group;" ::: "memory")
#define CP_WAIT0()  asm volatile("cp.async.wait_group 0;" ::: "memory")
#define CP_WAIT1()  asm volatile("cp.async.wait_group 1;" ::: "memory")

// ---------------- weight/activation split kernel ------------------------------
__global__ void conv_kernel(const float* __restrict__ w,
                            uint32_t* __restrict__ h,
                            uint32_t* __restrict__ l, int npairs) {
    int i = blockIdx.x * 256 + threadIdx.x;
    if (i < npairs) {
        float2 x = ((const float2*)w)[i];
        uint32_t hv, lv;
        split2(x.x, x.y, hv, lv);
        h[i] = hv; l[i] = lv;
    }
}

// ---------------- flash attention (fused QK^T + softmax + AV) ------------------
// grid (TT/128, BB*HH), block 256 = 8 warps; warp w owns q-rows [w*16, w*16+16).
// K-loop: 16 tiles of 64 tokens; K and V^T both streamed via cp.async (2 stages).
// P stays in registers: S-accumulator fragments repacked directly into
// A-operand fragments (bit-identical to the smem round-trip), removing the
// per-tile P stores/ldmatrix and the second __syncthreads.
// SMEM (words): stage s @ s*9216: Kh 0 | Kl 2304 | Vh 4608 | Vl 6912.
//               Q staging: @18432(hi), @23040(lo). Total 27648 words = 110592 B.
__global__ void __launch_bounds__(256) flash_attn(
    const uint32_t* __restrict__ qh_g, const uint32_t* __restrict__ ql_g,
    const uint32_t* __restrict__ vth,  const uint32_t* __restrict__ vtl,
    uint32_t* __restrict__ aoh, uint32_t* __restrict__ aol)
{
    extern __shared__ __align__(16) uint32_t dsm[];
    const int tid = threadIdx.x, lane = tid & 31, w = tid >> 5;
    const int bh = blockIdx.y, b = bh / HH, h = bh % HH;
    const int m0 = blockIdx.x * 128;
    const long tokb = (long)b * TT;
    const int hq = h * DHP;
    const int hk = CCP + h * DHP;
    const size_t vtb = (size_t)bh * DH * TTP;
    const uint32_t smb = smem_u32(dsm);
    const int qr = lane >> 2, kp = lane & 3;

    // ---- stage Q and load register fragments ----
    for (int i = 0; i < 4; i++) {
        const int idx = tid + i * 256;            // 0..1023
        const int row = idx >> 3, ch = idx & 7;
        const size_t src = (size_t)(tokb + m0 + row) * C3P + hq + ch * 4;
        *(uint4*)&dsm[18432 + row * 36 + ch * 4] = *(const uint4*)(qh_g + src);
        *(uint4*)&dsm[23040 + row * 36 + ch * 4] = *(const uint4*)(ql_g + src);
    }
    __syncthreads();
    uint32_t qfh[4][4], qfl[4][4];
    {
        const uint32_t ao = smb + (uint32_t)(w * 16 + (lane & 15)) * 144 +
                            (uint32_t)(lane >> 4) * 16;
        for (int j = 0; j < 4; j++) {
            ldm4(qfh[j], ao + 18432 * 4 + j * 32);
            ldm4(qfl[j], ao + 23040 * 4 + j * 32);
        }
    }
    __syncthreads();

    // ---- K + V^T prefetch via cp.async ----
    auto issueK = [&](int kt) {
        const uint32_t stb = smb + (uint32_t)(kt & 1) * (9216 * 4);
        for (int i = 0; i < 2; i++) {
            const int idx = tid + i * 256;         // 0..511
            const int row = idx >> 3, ch = idx & 7;
            const size_t ksrc = (size_t)(tokb + kt * 64 + row) * C3P + hk + ch * 4;
            const uint32_t kdst = stb + (uint32_t)row * 144 + (uint32_t)ch * 16;
            cp16(kdst, qh_g + ksrc);
            cp16(kdst + 2304 * 4, ql_g + ksrc);
            const size_t vsrc = vtb + (size_t)row * TTP + kt * 32 + ch * 4;
            const uint32_t vdst = kdst + 4608 * 4;
            cp16(vdst, vth + vsrc);
            cp16(vdst + 2304 * 4, vtl + vsrc);
        }
        CP_COMMIT();
    };
    issueK(0);

    float O[8][4];
#pragma unroll
    for (int nt = 0; nt < 8; nt++)
#pragma unroll
        for (int e = 0; e < 4; e++) O[nt][e] = 0.0f;
    float m0r = -1e30f, m1r = -1e30f, l0 = 0.0f, l1 = 0.0f;

    const uint32_t bof = (uint32_t)(((lane >> 4) & 1) * 8 + (lane & 7)) * 144 +
                         (uint32_t)((lane >> 3) & 1) * 16;

    for (int kt = 0; kt < 16; kt++) {
        CP_WAIT0();
        __syncthreads();                           // K/V[kt] ready; all warps past kt-1
        if (kt + 1 < 16) issueK(kt + 1);

        // ---- S = Q K^T (raw, scale folded into exp) ----
        float sacc[8][4];
#pragma unroll
        for (int nt = 0; nt < 8; nt++)
#pragma unroll
            for (int e = 0; e < 4; e++) sacc[nt][e] = 0.0f;
        const uint32_t stb = smb + (uint32_t)(kt & 1) * (9216 * 4);
#pragma unroll
        for (int g = 0; g < 4; g++)
#pragma unroll
            for (int j = 0; j < 4; j++) {
                uint32_t kb[4], kl[4];
                ldm4(kb, stb + bof + g * (16 * 144) + j * 32);
                ldm4(kl, stb + 2304 * 4 + bof + g * (16 * 144) + j * 32);
#pragma unroll
                for (int t = 0; t < 2; t++) {
                    const int nt = 2 * g + t;
                    mma16(sacc[nt], qfh[j], &kl[2 * t]);
                    mma16(sacc[nt], qfl[j], &kb[2 * t]);
                    mma16(sacc[nt], qfh[j], &kb[2 * t]);
                }
            }

        // ---- online softmax -> P directly into A-fragment registers ----
        float tm0 = -1e30f, tm1 = -1e30f;
#pragma unroll
        for (int nt = 0; nt < 8; nt++) {
            tm0 = fmaxf(tm0, fmaxf(sacc[nt][0], sacc[nt][1]));
            tm1 = fmaxf(tm1, fmaxf(sacc[nt][2], sacc[nt][3]));
        }
        tm0 = fmaxf(tm0, __shfl_xor_sync(0xffffffff, tm0, 1));
        tm0 = fmaxf(tm0, __shfl_xor_sync(0xffffffff, tm0, 2));
        tm1 = fmaxf(tm1, __shfl_xor_sync(0xffffffff, tm1, 1));
        tm1 = fmaxf(tm1, __shfl_xor_sync(0xffffffff, tm1, 2));
        const float mn0 = fmaxf(m0r, tm0 * 0.125f);
        const float mn1 = fmaxf(m1r, tm1 * 0.125f);
        const float f0 = exp2f((m0r - mn0) * LOG2E);
        const float f1 = exp2f((m1r - mn1) * LOG2E);
        m0r = mn0; m1r = mn1;
        const float mm0 = mn0 * LOG2E, mm1 = mn1 * LOG2E;
        float s0 = 0.0f, s1 = 0.0f;
        uint32_t pfh[4][4], pfl[4][4];
#pragma unroll
        for (int nt = 0; nt < 8; nt++) {
            const float p0 = exp2f(fmaf(sacc[nt][0], SEXP, -mm0));
            const float p1 = exp2f(fmaf(sacc[nt][1], SEXP, -mm0));
            const float p2 = exp2f(fmaf(sacc[nt][2], SEXP, -mm1));
            const float p3 = exp2f(fmaf(sacc[nt][3], SEXP, -mm1));
            s0 += p0 + p1; s1 += p2 + p3;
            const int j = nt >> 1;
            if ((nt & 1) == 0) {
                split2(p0, p1, pfh[j][0], pfl[j][0]);   // (qr,   lower 8 tokens)
                split2(p2, p3, pfh[j][1], pfl[j][1]);   // (qr+8, lower 8 tokens)
            } else {
                split2(p0, p1, pfh[j][2], pfl[j][2]);   // (qr,   upper 8 tokens)
                split2(p2, p3, pfh[j][3], pfl[j][3]);   // (qr+8, upper 8 tokens)
            }
        }
        s0 += __shfl_xor_sync(0xffffffff, s0, 1);
        s0 += __shfl_xor_sync(0xffffffff, s0, 2);
        s1 += __shfl_xor_sync(0xffffffff, s1, 1);
        s1 += __shfl_xor_sync(0xffffffff, s1, 2);
        l0 = l0 * f0 + s0;
        l1 = l1 * f1 + s1;
#pragma unroll
        for (int nt = 0; nt < 8; nt++) {
            O[nt][0] *= f0; O[nt][1] *= f0;
            O[nt][2] *= f1; O[nt][3] *= f1;
        }

        // ---- O += P V (P from registers; no smem round-trip, no barrier) ----
#pragma unroll
        for (int j = 0; j < 4; j++) {
#pragma unroll
            for (int g = 0; g < 4; g++) {
                uint32_t vbh[4], vbl[4];
                ldm4(vbh, stb + 4608 * 4 + bof + g * (16 * 144) + j * 32);
                ldm4(vbl, stb + 6912 * 4 + bof + g * (16 * 144) + j * 32);
#pragma unroll
                for (int t = 0; t < 2; t++) {
                    const int nt = 2 * g + t;
                    mma16(O[nt], pfh[j], &vbl[2 * t]);
                    mma16(O[nt], pfl[j], &vbh[2 * t]);
                    mma16(O[nt], pfh[j], &vbh[2 * t]);
                }
            }
        }
    }

    // ---- epilogue: O /= l, write attention-out planes ----
    const float il0 = 1.0f / l0, il1 = 1.0f / l1;
    const size_t r0g = (size_t)(tokb + m0 + w * 16 + qr) * CCP + hq + kp;
    const size_t r1g = r0g + (size_t)8 * CCP;
#pragma unroll
    for (int nt = 0; nt < 8; nt++) {
        uint32_t hh, ll;
        split2(O[nt][0] * il0, O[nt][1] * il0, hh, ll);
        aoh[r0g + nt * 4] = hh; aol[r0g + nt * 4] = ll;
        split2(O[nt][2] * il1, O[nt][3] * il1, hh, ll);
        aoh[r1g + nt * 4] = hh; aol[r1g + nt * 4] = ll;
    }
}

// ---------------- unified tensor-core GEMM (bf16x3, cp.async 3-stage) ---------
// out[m,n] = sum_k A[m,k] * B[n,k]   (planes pre-split, pairs packed along k).
// Tile: 128(M) x 64(N) x 16(K), 8 warps (4x2), warp tile 32x32.
// MODE: 0 +bias | 1 gelu(+bias) | 2 +bias+add1 | 3 +bias+add1-add2
// VOUT: tiles with n0 >= 2*CC write V^T planes (token-paired) instead.
template<int MODE, bool OUTP, bool VOUT>
__global__ void __launch_bounds__(256, 3) mma_gemm(
    const uint32_t* __restrict__ Agh, const uint32_t* __restrict__ Agl,
    const uint32_t* __restrict__ Bgh, const uint32_t* __restrict__ Bgl,
    const float* __restrict__ bias,
    float* __restrict__ outF, uint32_t* __restrict__ outH, uint32_t* __restrict__ outL,
    uint32_t* __restrict__ vth, uint32_t* __restrict__ vtl,
    int K, int ldaP, int ldbP, int ldc,
    const float* __restrict__ add1, const float* __restrict__ add2)
{
    extern __shared__ __align__(16) uint32_t dsm[];
    constexpr uint32_t STB     = 18432;      // bytes/stage
    constexpr uint32_t OFF_AL  = 6144;
    constexpr uint32_t OFF_BH  = 12288;
    constexpr uint32_t OFF_BL  = 15360;

    const int tid  = threadIdx.x;
    const int lane = tid & 31;
    const int wid  = tid >> 5;
    const int wm   = wid >> 1;
    const int wn   = wid & 1;
    const int m0   = blockIdx.y * 128;
    const int n0   = blockIdx.x * 64;

    const int nsteps = K >> 4;

    const int arow = tid >> 1;
    const int akq  = (tid & 1) << 2;

    const uint32_t smb = smem_u32(dsm);
    const uint32_t aoff = (uint32_t)(wm * 32 + (lane & 15)) * 48 + (uint32_t)(lane >> 4) * 16;
    const uint32_t boff = (uint32_t)(wn * 32 + ((lane >> 4) & 1) * 8 + (lane & 7)) * 48 +
                          (uint32_t)((lane >> 3) & 1) * 16;

    auto issue = [&](int s, int st) {
        const uint32_t stb = smb + (uint32_t)st * STB;
        const size_t aog = (size_t)(m0 + arow) * ldaP + (s << 3) + akq;
        const uint32_t adst = stb + (uint32_t)arow * 48 + (uint32_t)akq * 4;
        cp16(adst, Agh + aog);
        cp16(adst + OFF_AL, Agl + aog);
        if (tid < 128) {
            const int br = tid >> 1;
            const size_t bog = (size_t)(n0 + br) * ldbP + (s << 3) + akq;
            const uint32_t bdst = stb + OFF_BH + (uint32_t)br * 48 + (uint32_t)akq * 4;
            cp16(bdst, Bgh + bog);
            cp16(bdst + (OFF_BL - OFF_BH), Bgl + bog);
        }
    };

    // prologue: stages 0,1
    issue(0, 0); CP_COMMIT();
    if (1 < nsteps) issue(1, 1);
    CP_COMMIT();

    float acc[2][4][4];
#pragma unroll
    for (int i = 0; i < 2; i++)
#pragma unroll
        for (int j = 0; j < 4; j++)
#pragma unroll
            for (int e = 0; e < 4; e++) acc[i][j][e] = 0.0f;

    const int kp = lane & 3;
    const int qr = lane >> 2;

    int st = 0, stn = 2;          // current stage, next-issue stage (mod 3)
    for (int s = 0; s < nsteps; s++) {
        CP_WAIT1();
        __syncthreads();
        if (s + 2 < nsteps) issue(s + 2, stn);
        CP_COMMIT();

        const uint32_t stb = smb + (uint32_t)st * STB;
        uint32_t ah[2][4], al4[2][4];
#pragma unroll
        for (int mt = 0; mt < 2; mt++) {
            const uint32_t ao = aoff + (uint32_t)mt * 768;
            ldm4(ah[mt],  stb + ao);
            ldm4(al4[mt], stb + OFF_AL + ao);
        }
        uint32_t bfh[2][4], bfl[2][4];
#pragma unroll
        for (int ntp = 0; ntp < 2; ntp++) {
            const uint32_t bo = boff + (uint32_t)ntp * 768;
            ldm4(bfh[ntp], stb + OFF_BH + bo);
            ldm4(bfl[ntp], stb + OFF_BL + bo);
        }
#pragma unroll
        for (int mt = 0; mt < 2; mt++)
#pragma unroll
            for (int ntp = 0; ntp < 2; ntp++)
#pragma unroll
                for (int j = 0; j < 2; j++) {
                    const int nt = 2 * ntp + j;
                    mma16(acc[mt][nt], ah[mt],  &bfl[ntp][2 * j]);
                    mma16(acc[mt][nt], al4[mt], &bfh[ntp][2 * j]);
                    mma16(acc[mt][nt], ah[mt],  &bfh[ntp][2 * j]);
                }

        st = (st == 2) ? 0 : st + 1;
        stn = (stn == 2) ? 0 : stn + 1;
    }

    // ---- epilogue ------------------------------------------------------------
    const bool vtile = VOUT && (n0 >= 2 * CC);
#pragma unroll
    for (int mt = 0; mt < 2; mt++) {
#pragma unroll
        for (int nt = 0; nt < 4; nt++) {
            const int r = m0 + wm * 32 + mt * 16 + qr;
            const int c = n0 + wn * 32 + nt * 8 + 2 * kp;
            float vv[4];
#pragma unroll
            for (int e = 0; e < 4; e++) {
                const int cc = c + (e & 1);
                float v = acc[mt][nt][e];
                v += bias[cc];
                if (MODE == 1) v = 0.5f * v * (1.0f + erff(v * 0.70710678118654752f));
                vv[e] = v;
            }
            if (vtile) {
                // V^T planes: pairs along tokens via lane exchange (qr bit0)
                const float o0 = __shfl_xor_sync(0xffffffff, vv[0], 4);
                const float o1 = __shfl_xor_sync(0xffffffff, vv[1], 4);
                const float o2 = __shfl_xor_sync(0xffffffff, vv[2], 4);
                const float o3 = __shfl_xor_sync(0xffffffff, vv[3], 4);
                const int b = m0 >> 10;
                const int head = (n0 - 2 * CC) >> 6;
                const int t = r - (b << 10);
                const int d = c - n0;
                const size_t base = (size_t)(b * HH + head) * (DH * TTP) +
                                    (size_t)d * TTP;
                uint32_t hh, ll;
                if ((qr & 1) == 0) {
                    const int tp = t >> 1;
                    split2(vv[0], o0, hh, ll);
                    vth[base + tp] = hh;        vtl[base + tp] = ll;
                    split2(vv[1], o1, hh, ll);
                    vth[base + TTP + tp] = hh;  vtl[base + TTP + tp] = ll;
                } else {
                    const int tp = (t + 7) >> 1;      // even token t-1+8
                    split2(o2, vv[2], hh, ll);
                    vth[base + tp] = hh;        vtl[base + tp] = ll;
                    split2(o3, vv[3], hh, ll);
                    vth[base + TTP + tp] = hh;  vtl[base + TTP + tp] = ll;
                }
            } else if (OUTP) {
                const int cp = c >> 1;
                uint32_t h0, l0, h1, l1;
                split2(vv[0], vv[1], h0, l0);
                split2(vv[2], vv[3], h1, l1);
                outH[(size_t)r * ldc + cp] = h0;
                outL[(size_t)r * ldc + cp] = l0;
                outH[(size_t)(r + 8) * ldc + cp] = h1;
                outL[(size_t)(r + 8) * ldc + cp] = l1;
            } else {
#pragma unroll
                for (int e = 0; e < 4; e++) {
                    const int rr = r + (e >> 1) * 8;
                    const int cc = c + (e & 1);
                    const size_t oidx = (size_t)rr * ldc + cc;
                    float v = vv[e];
                    if (MODE == 2) v += add1[oidx];
                    if (MODE == 3) v += add1[oidx] - add2[oidx];
                    outF[oidx] = v;
                }
            }
        }
    }
}

// ---------------- fused add + LayerNorm -> hi/lo planes -----------------------
__global__ void ln_kernel(const float* __restrict__ zin,
                          const float* __restrict__ u,
                          const float* __restrict__ emb,
                          const float* __restrict__ w,
                          const float* __restrict__ b,
                          uint32_t* __restrict__ oh,
                          uint32_t* __restrict__ ol) {
    __shared__ float red[256];
    const int row = blockIdx.x;
    const int tid = threadIdx.x;
    const size_t base = (size_t)row * CC;
    const float2* z2 = (const float2*)(zin + base);
    const float2* u2 = u ? (const float2*)(u + base) : nullptr;
    const float2* e2 = emb ? (const float2*)emb : nullptr;

    float2 va = z2[tid];
    float2 vb = make_float2(0.f, 0.f);
    if (u2) { float2 t = u2[tid]; va.x += t.x; va.y += t.y; }
    if (e2) { float2 t = e2[tid]; va.x += 0.1f * t.x; va.y += 0.1f * t.y; }
    if (tid < 128) {
        vb = z2[256 + tid];
        if (u2) { float2 t = u2[256 + tid]; vb.x += t.x; vb.y += t.y; }
        if (e2) { float2 t = e2[256 + tid]; vb.x += 0.1f * t.x; vb.y += 0.1f * t.y; }
    }
    float s = va.x + va.y + vb.x + vb.y;
    red[tid] = s; __syncthreads();
    for (int st = 128; st > 0; st >>= 1) {
        if (tid < st) red[tid] += red[tid + st];
        __syncthreads();
    }
    const float mu = red[0] * (1.0f / CC);
    __syncthreads();
    va.x -= mu; va.y -= mu;
    float s2 = va.x * va.x + va.y * va.y;
    if (tid < 128) { vb.x -= mu; vb.y -= mu; s2 += vb.x * vb.x + vb.y * vb.y; }
    red[tid] = s2; __syncthreads();
    for (int st = 128; st > 0; st >>= 1) {
        if (tid < st) red[tid] += red[tid + st];
        __syncthreads();
    }
    const float rs = rsqrtf(red[0] * (1.0f / CC) + 1e-5f);

    const float2* w2 = (const float2*)w;
    const float2* b2 = (const float2*)b;
    {
        float2 wc = w2[tid], bc = b2[tid];
        float y0 = va.x * rs * wc.x + bc.x;
        float y1 = va.y * rs * wc.y + bc.y;
        uint32_t hv, lv;
        split2(y0, y1, hv, lv);
        oh[(size_t)row * CCP + tid] = hv;
        ol[(size_t)row * CCP + tid] = lv;
    }
    if (tid < 128) {
        float2 wc = w2[256 + tid], bc = b2[256 + tid];
        float y0 = vb.x * rs * wc.x + bc.x;
        float y1 = vb.y * rs * wc.y + bc.y;
        uint32_t hv, lv;
        split2(y0, y1, hv, lv);
        oh[(size_t)row * CCP + 256 + tid] = hv;
        ol[(size_t)row * CCP + 256 + tid] = lv;
    }
}

// ---------------- Anderson acceleration update (one block per token) ---------
__global__ void anderson_kernel(float* __restrict__ z,
                                const float* __restrict__ res,
                                float* __restrict__ fh, int it) {
    __shared__ float sh[14][256];
    __shared__ float alpha_sh[4];
    const int n = blockIdx.x, tid = threadIdx.x;
    const size_t base = (size_t)n * CC;
    const int K = it < 4 ? it : 4;
    const int c0 = tid, c1 = tid + 256, c2 = tid + 512;

    float r0 = res[base + c0], r1 = res[base + c1], r2 = res[base + c2];
    float dF[4][3];
    for (int j = 0; j < K; j++) {
        const int slot = (it - K + j) & 3;
        const float* f = fh + (size_t)slot * ZSZ + base;
        dF[j][0] = f[c0] - r0; dF[j][1] = f[c1] - r1; dF[j][2] = f[c2] - r2;
    }

    if (K > 0) {
        int idx = 0;
        for (int k = 0; k < K; k++)
            for (int l = k; l < K; l++) {
                sh[idx][tid] = dF[k][0] * dF[l][0] + dF[k][1] * dF[l][1] + dF[k][2] * dF[l][2];
                idx++;
            }
        for (int k = 0; k < K; k++) {
            sh[idx][tid] = dF[k][0] * r0 + dF[k][1] * r1 + dF[k][2] * r2;
            idx++;
        }
        const int np = idx;
        __syncthreads();
        for (int st = 128; st > 0; st >>= 1) {
            if (tid < st)
                for (int v = 0; v < np; v++) sh[v][tid] += sh[v][tid + st];
            __syncthreads();
        }
        if (tid == 0) {
            float G[4][4], bv[4], al[4];
            int id2 = 0;
            for (int k = 0; k < K; k++)
                for (int l = k; l < K; l++) { G[k][l] = G[l][k] = sh[id2][0]; id2++; }
            for (int k = 0; k < K; k++) { G[k][k] += 1e-6f; bv[k] = sh[id2][0]; id2++; }
            for (int p = 0; p < K; p++) {
                const float inv = 1.0f / G[p][p];
                for (int rr = p + 1; rr < K; rr++) {
                    const float f2 = G[rr][p] * inv;
                    for (int cc = p; cc < K; cc++) G[rr][cc] -= f2 * G[p][cc];
                    bv[rr] -= f2 * bv[p];
                }
            }
            for (int p = K - 1; p >= 0; p--) {
                float s = bv[p];
                for (int cc = p + 1; cc < K; cc++) s -= G[p][cc] * al[cc];
                al[p] = s / G[p][p];
            }
            for (int k = 0; k < K; k++) alpha_sh[k] = al[k];
        }
        __syncthreads();
        float d0 = r0, d1 = r1, d2 = r2;
        for (int j = 0; j < K; j++) {
            const float a = alpha_sh[j];
            d0 -= a * dF[j][0]; d1 -= a * dF[j][1]; d2 -= a * dF[j][2];
        }
        z[base + c0] += d0; z[base + c1] += d1; z[base + c2] += d2;
    } else {
        z[base + c0] += r0; z[base + c1] += r1; z[base + c2] += r2;
    }

    float* fs = fh + (size_t)(it & 3) * ZSZ + base;
    fs[c0] = r0; fs[c1] = r1; fs[c2] = r2;
}

// ---------------- host launcher ----------------------------------------------
template <typename T>
static T* symaddr(const void* s) {
    void* p = nullptr;
    cudaGetSymbolAddress(&p, s);
    return (T*)p;
}

#define GEMM_SMEM  55296
#define FLASH_SMEM 110592

extern "C" void kernel_launch(void* const* d_in, const int* in_sizes, int n_in,
                              void* d_out, int out_size) {
    const float* u          = (const float*)d_in[0];
    const float* iter_emb   = (const float*)d_in[1];
    const float* ln1_w      = (const float*)d_in[2];
    const float* ln1_b      = (const float*)d_in[3];
    const float* in_proj_w  = (const float*)d_in[4];
    const float* in_proj_b  = (const float*)d_in[5];
    const float* out_proj_w = (const float*)d_in[6];
    const float* out_proj_b = (const float*)d_in[7];
    const float* ln2_w      = (const float*)d_in[8];
    const float* ln2_b      = (const float*)d_in[9];
    const float* mlp_w1     = (const float*)d_in[10];
    const float* mlp_b1     = (const float*)d_in[11];
    const float* mlp_w2     = (const float*)d_in[12];
    const float* mlp_b2     = (const float*)d_in[13];
    // d_in[14] = num_iters (fixed to 6 by setup_inputs)

    float* zp   = symaddr<float>(g_z);
    float* zap  = symaddr<float>(g_zattn);
    float* resp = symaddr<float>(g_res);
    float* fhp  = symaddr<float>(g_fhist);
    uint32_t* xh   = symaddr<uint32_t>(g_x_h);    uint32_t* xl   = symaddr<uint32_t>(g_x_l);
    uint32_t* qh   = symaddr<uint32_t>(g_qkv_h);  uint32_t* ql   = symaddr<uint32_t>(g_qkv_l);
    uint32_t* vth  = symaddr<uint32_t>(g_vt_h);   uint32_t* vtl  = symaddr<uint32_t>(g_vt_l);
    uint32_t* aoh  = symaddr<uint32_t>(g_ao_h);   uint32_t* aol  = symaddr<uint32_t>(g_ao_l);
    uint32_t* mih  = symaddr<uint32_t>(g_mid_h);  uint32_t* mil  = symaddr<uint32_t>(g_mid_l);
    uint32_t* wqh  = symaddr<uint32_t>(g_wqkv_h); uint32_t* wql  = symaddr<uint32_t>(g_wqkv_l);
    uint32_t* woh  = symaddr<uint32_t>(g_wo_h);   uint32_t* wol  = symaddr<uint32_t>(g_wo_l);
    uint32_t* w1h  = symaddr<uint32_t>(g_w1_h);   uint32_t* w1l  = symaddr<uint32_t>(g_w1_l);
    uint32_t* w2h  = symaddr<uint32_t>(g_w2_h);   uint32_t* w2l  = symaddr<uint32_t>(g_w2_l);

    cudaFuncSetAttribute((const void*)mma_gemm<0, true,  true >, cudaFuncAttributeMaxDynamicSharedMemorySize, GEMM_SMEM);
    cudaFuncSetAttribute((const void*)mma_gemm<2, false, false>, cudaFuncAttributeMaxDynamicSharedMemorySize, GEMM_SMEM);
    cudaFuncSetAttribute((const void*)mma_gemm<1, true,  false>, cudaFuncAttributeMaxDynamicSharedMemorySize, GEMM_SMEM);
    cudaFuncSetAttribute((const void*)mma_gemm<3, false, false>, cudaFuncAttributeMaxDynamicSharedMemorySize, GEMM_SMEM);
    cudaFuncSetAttribute((const void*)flash_attn, cudaFuncAttributeMaxDynamicSharedMemorySize, FLASH_SMEM);

    cudaMemsetAsync(zp, 0, (size_t)ZSZ * sizeof(float), 0);

    // split weights once per launch
    conv_kernel<<<(C3 * CCP + 255) / 256, 256>>>(in_proj_w,  wqh, wql, C3 * CCP);
    conv_kernel<<<(CC * CCP + 255) / 256, 256>>>(out_proj_w, woh, wol, CC * CCP);
    conv_kernel<<<(C4 * CCP + 255) / 256, 256>>>(mlp_w1,     w1h, w1l, C4 * CCP);
    conv_kernel<<<(CC * C4P + 255) / 256, 256>>>(mlp_w2,     w2h, w2l, CC * C4P);

    for (int it = 0; it < NUM_ITERS; it++) {
        // x = LN1(z + 0.1*emb[it] + u) -> planes
        ln_kernel<<<BT, 256>>>(zp, u, iter_emb + it * CC, ln1_w, ln1_b, xh, xl);

        // qkv = x @ Wqkv^T + b -> Q/K planes; V tiles write V^T planes directly
        mma_gemm<0, true, true><<<dim3(C3 / 64, BT / 128), 256, GEMM_SMEM>>>(
            xh, xl, wqh, wql, in_proj_b, nullptr, qh, ql, vth, vtl,
            CC, CCP, CCP, C3P, nullptr, nullptr);

        // fused attention: softmax(QK^T/8) @ V  -> planes
        flash_attn<<<dim3(TT / 128, BB * HH), 256, FLASH_SMEM>>>(qh, ql, vth, vtl, aoh, aol);

        // z_attn = z + attnout @ Wo^T + bo  (fp32)
        mma_gemm<2, false, false><<<dim3(CC / 64, BT / 128), 256, GEMM_SMEM>>>(
            aoh, aol, woh, wol, out_proj_b, zap, nullptr, nullptr, nullptr, nullptr,
            CC, CCP, CCP, CC, zp, nullptr);

        // h = LN2(z_attn) -> planes
        ln_kernel<<<BT, 256>>>(zap, nullptr, nullptr, ln2_w, ln2_b, xh, xl);

        // mid = gelu(h @ W1^T + b1) -> planes
        mma_gemm<1, true, false><<<dim3(C4 / 64, BT / 128), 256, GEMM_SMEM>>>(
            xh, xl, w1h, w1l, mlp_b1, nullptr, mih, mil, nullptr, nullptr,
            CC, CCP, CCP, C4P, nullptr, nullptr);

        // res = (mid @ W2^T + b2) + z_attn - z  (fp32)
        mma_gemm<3, false, false><<<dim3(CC / 64, BT / 128), 256, GEMM_SMEM>>>(
            mih, mil, w2h, w2l, mlp_b2, resp, nullptr, nullptr, nullptr, nullptr,
            C4, C4P, C4P, CC, zap, zp);

        // Anderson update of z, residual history push
        anderson_kernel<<<BT, 256>>>(zp, resp, fhp, it);
    }

    cudaMemcpyAsync(d_out, zp, (size_t)ZSZ * sizeof(float),
                    cudaMemcpyDeviceToDevice, 0);
}

// round 16
// speedup vs baseline: 1.0362x; 1.0091x over previous
#include <cuda_runtime.h>
#include <cuda_bf16.h>
#include <math.h>
#include <stdint.h>

// Problem constants (fixed by setup_inputs)
#define BB    4
#define TT    1024
#define CC    768
#define HH    12
#define DH    64
#define BT    4096            // B*T
#define C3    2304            // 3*C
#define C4    3072            // 4*C
#define ZSZ   3145728         // BT*C
#define NUM_ITERS 6
// pair (bf16x2) leading dims
#define CCP   384
#define C3P   1152
#define C4P   1536
#define TTP   512
#define DHP   32

#define LOG2E 1.4426950408889634f
#define SEXP  0.18033688011112042f    // 0.125 * log2(e)

// ---------------- scratch (device globals; no allocation allowed) -----------
__device__ float g_z[ZSZ];
__device__ float g_zattn[ZSZ];
__device__ float g_res[ZSZ];
__device__ float g_fhist[4 * ZSZ];

// hi/lo bf16x2 planes (pairs packed along k)
__device__ uint32_t g_x_h[BT * CCP],    g_x_l[BT * CCP];
__device__ uint32_t g_qkv_h[BT * C3P],  g_qkv_l[BT * C3P];
__device__ uint32_t g_vt_h[BB * HH * DH * TTP], g_vt_l[BB * HH * DH * TTP];
__device__ uint32_t g_ao_h[BT * CCP],   g_ao_l[BT * CCP];
__device__ uint32_t g_mid_h[BT * C4P],  g_mid_l[BT * C4P];
// weight planes (split once per launch)
__device__ uint32_t g_wqkv_h[C3 * CCP], g_wqkv_l[C3 * CCP];
__device__ uint32_t g_wo_h[CC * CCP],   g_wo_l[CC * CCP];
__device__ uint32_t g_w1_h[C4 * CCP],   g_w1_l[C4 * CCP];
__device__ uint32_t g_w2_h[CC * C4P],   g_w2_l[CC * C4P];

// ---------------- helpers ------------------------------------------------------
__device__ __forceinline__ void split2(float x, float y, uint32_t& hi, uint32_t& lo) {
    __nv_bfloat162 h2 = __floats2bfloat162_rn(x, y);
    float lx = x - __low2float(h2);
    float ly = y - __high2float(h2);
    __nv_bfloat162 l2 = __floats2bfloat162_rn(lx, ly);
    hi = *reinterpret_cast<uint32_t*>(&h2);
    lo = *reinterpret_cast<uint32_t*>(&l2);
}

__device__ __forceinline__ void mma16(float c[4], const uint32_t a[4], const uint32_t b[2]) {
    asm volatile(
        "mma.sync.aligned.m16n8k16.row.col.f32.bf16.bf16.f32 "
        "{%0,%1,%2,%3}, {%4,%5,%6,%7}, {%8,%9}, {%0,%1,%2,%3};\n"
        : "+f"(c[0]), "+f"(c[1]), "+f"(c[2]), "+f"(c[3])
        : "r"(a[0]), "r"(a[1]), "r"(a[2]), "r"(a[3]), "r"(b[0]), "r"(b[1]));
}

__device__ __forceinline__ void ldm4(uint32_t r[4], uint32_t addr) {
    asm volatile("ldmatrix.sync.aligned.m8n8.x4.shared.b16 {%0,%1,%2,%3}, [%4];"
        : "=r"(r[0]), "=r"(r[1]), "=r"(r[2]), "=r"(r[3]) : "r"(addr));
}

__device__ __forceinline__ uint32_t smem_u32(const void* p) {
    return (uint32_t)__cvta_generic_to_shared(p);
}

__device__ __forceinline__ void cp16(uint32_t dst, const uint32_t* src) {
    asm volatile("cp.async.cg.shared.global [%0], [%1], 16;" :: "r"(dst), "l"(src));
}
#define CP_COMMIT() asm volatile("cp.async.commit_group;" ::: "memory")
#define CP_WAIT0()  asm volatile("cp.async.wait_group 0;" ::: "memory")
#define CP_WAIT1()  asm volatile("cp.async.wait_group 1;" ::: "memory")

// ---------------- weight/activation split kernel ------------------------------
__global__ void conv_kernel(const float* __restrict__ w,
                            uint32_t* __restrict__ h,
                            uint32_t* __restrict__ l, int npairs) {
    int i = blockIdx.x * 256 + threadIdx.x;
    if (i < npairs) {
        float2 x = ((const float2*)w)[i];
        uint32_t hv, lv;
        split2(x.x, x.y, hv, lv);
        h[i] = hv; l[i] = lv;
    }
}

// ---------------- flash attention (fused QK^T + softmax + AV) ------------------
// grid (TT/128, BB*HH), block 256 = 8 warps; warp w owns q-rows [w*16, w*16+16).
// K-loop: 16 tiles of 64 tokens; K and V^T streamed via cp.async (2 stages).
// P stays in registers (S-fragments repacked into A-fragments, bit-identical).
// Q is staged through the stage-1 K/V buffer (consumed into registers before
// stage 1's first cp.async write), so SMEM = 2 stages only:
//   stage s @ s*9216 words: Kh 0 | Kl 2304 | Vh 4608 | Vl 6912.
// Total 18432 words = 73728 B -> 2 CTAs/SM (launch_bounds(256,2)).
__global__ void __launch_bounds__(256, 2) flash_attn(
    const uint32_t* __restrict__ qh_g, const uint32_t* __restrict__ ql_g,
    const uint32_t* __restrict__ vth,  const uint32_t* __restrict__ vtl,
    uint32_t* __restrict__ aoh, uint32_t* __restrict__ aol)
{
    extern __shared__ __align__(16) uint32_t dsm[];
    const int tid = threadIdx.x, lane = tid & 31, w = tid >> 5;
    const int bh = blockIdx.y, b = bh / HH, h = bh % HH;
    const int m0 = blockIdx.x * 128;
    const long tokb = (long)b * TT;
    const int hq = h * DHP;
    const int hk = CCP + h * DHP;
    const size_t vtb = (size_t)bh * DH * TTP;
    const uint32_t smb = smem_u32(dsm);
    const int qr = lane >> 2, kp = lane & 3;

    // ---- stage Q into stage-1 region, load register fragments ----
    for (int i = 0; i < 4; i++) {
        const int idx = tid + i * 256;            // 0..1023
        const int row = idx >> 3, ch = idx & 7;
        const size_t src = (size_t)(tokb + m0 + row) * C3P + hq + ch * 4;
        *(uint4*)&dsm[9216 + row * 36 + ch * 4]        = *(const uint4*)(qh_g + src);
        *(uint4*)&dsm[9216 + 4608 + row * 36 + ch * 4] = *(const uint4*)(ql_g + src);
    }
    __syncthreads();
    uint32_t qfh[4][4], qfl[4][4];
    {
        const uint32_t ao = smb + (uint32_t)(w * 16 + (lane & 15)) * 144 +
                            (uint32_t)(lane >> 4) * 16;
        for (int j = 0; j < 4; j++) {
            ldm4(qfh[j], ao + 9216 * 4 + j * 32);
            ldm4(qfl[j], ao + (9216 + 4608) * 4 + j * 32);
        }
    }
    __syncthreads();                               // all warps done reading Q smem

    // ---- K + V^T prefetch via cp.async ----
    auto issueK = [&](int kt) {
        const uint32_t stb = smb + (uint32_t)(kt & 1) * (9216 * 4);
        for (int i = 0; i < 2; i++) {
            const int idx = tid + i * 256;         // 0..511
            const int row = idx >> 3, ch = idx & 7;
            const size_t ksrc = (size_t)(tokb + kt * 64 + row) * C3P + hk + ch * 4;
            const uint32_t kdst = stb + (uint32_t)row * 144 + (uint32_t)ch * 16;
            cp16(kdst, qh_g + ksrc);
            cp16(kdst + 2304 * 4, ql_g + ksrc);
            const size_t vsrc = vtb + (size_t)row * TTP + kt * 32 + ch * 4;
            const uint32_t vdst = kdst + 4608 * 4;
            cp16(vdst, vth + vsrc);
            cp16(vdst + 2304 * 4, vtl + vsrc);
        }
        CP_COMMIT();
    };
    issueK(0);

    float O[8][4];
#pragma unroll
    for (int nt = 0; nt < 8; nt++)
#pragma unroll
        for (int e = 0; e < 4; e++) O[nt][e] = 0.0f;
    float m0r = -1e30f, m1r = -1e30f, l0 = 0.0f, l1 = 0.0f;

    const uint32_t bof = (uint32_t)(((lane >> 4) & 1) * 8 + (lane & 7)) * 144 +
                         (uint32_t)((lane >> 3) & 1) * 16;

    for (int kt = 0; kt < 16; kt++) {
        CP_WAIT0();
        __syncthreads();                           // K/V[kt] ready; all warps past kt-1
        if (kt + 1 < 16) issueK(kt + 1);

        // ---- S = Q K^T (raw, scale folded into exp) ----
        float sacc[8][4];
#pragma unroll
        for (int nt = 0; nt < 8; nt++)
#pragma unroll
            for (int e = 0; e < 4; e++) sacc[nt][e] = 0.0f;
        const uint32_t stb = smb + (uint32_t)(kt & 1) * (9216 * 4);
#pragma unroll
        for (int g = 0; g < 4; g++)
#pragma unroll
            for (int j = 0; j < 4; j++) {
                uint32_t kb[4], kl[4];
                ldm4(kb, stb + bof + g * (16 * 144) + j * 32);
                ldm4(kl, stb + 2304 * 4 + bof + g * (16 * 144) + j * 32);
#pragma unroll
                for (int t = 0; t < 2; t++) {
                    const int nt = 2 * g + t;
                    mma16(sacc[nt], qfh[j], &kl[2 * t]);
                    mma16(sacc[nt], qfl[j], &kb[2 * t]);
                    mma16(sacc[nt], qfh[j], &kb[2 * t]);
                }
            }

        // ---- online softmax -> P directly into A-fragment registers ----
        float tm0 = -1e30f, tm1 = -1e30f;
#pragma unroll
        for (int nt = 0; nt < 8; nt++) {
            tm0 = fmaxf(tm0, fmaxf(sacc[nt][0], sacc[nt][1]));
            tm1 = fmaxf(tm1, fmaxf(sacc[nt][2], sacc[nt][3]));
        }
        tm0 = fmaxf(tm0, __shfl_xor_sync(0xffffffff, tm0, 1));
        tm0 = fmaxf(tm0, __shfl_xor_sync(0xffffffff, tm0, 2));
        tm1 = fmaxf(tm1, __shfl_xor_sync(0xffffffff, tm1, 1));
        tm1 = fmaxf(tm1, __shfl_xor_sync(0xffffffff, tm1, 2));
        const float mn0 = fmaxf(m0r, tm0 * 0.125f);
        const float mn1 = fmaxf(m1r, tm1 * 0.125f);
        const float f0 = exp2f((m0r - mn0) * LOG2E);
        const float f1 = exp2f((m1r - mn1) * LOG2E);
        m0r = mn0; m1r = mn1;
        const float mm0 = mn0 * LOG2E, mm1 = mn1 * LOG2E;
        float s0 = 0.0f, s1 = 0.0f;
        uint32_t pfh[4][4], pfl[4][4];
#pragma unroll
        for (int nt = 0; nt < 8; nt++) {
            const float p0 = exp2f(fmaf(sacc[nt][0], SEXP, -mm0));
            const float p1 = exp2f(fmaf(sacc[nt][1], SEXP, -mm0));
            const float p2 = exp2f(fmaf(sacc[nt][2], SEXP, -mm1));
            const float p3 = exp2f(fmaf(sacc[nt][3], SEXP, -mm1));
            s0 += p0 + p1; s1 += p2 + p3;
            const int j = nt >> 1;
            if ((nt & 1) == 0) {
                split2(p0, p1, pfh[j][0], pfl[j][0]);   // (qr,   lower 8 tokens)
                split2(p2, p3, pfh[j][1], pfl[j][1]);   // (qr+8, lower 8 tokens)
            } else {
                split2(p0, p1, pfh[j][2], pfl[j][2]);   // (qr,   upper 8 tokens)
                split2(p2, p3, pfh[j][3], pfl[j][3]);   // (qr+8, upper 8 tokens)
            }
        }
        s0 += __shfl_xor_sync(0xffffffff, s0, 1);
        s0 += __shfl_xor_sync(0xffffffff, s0, 2);
        s1 += __shfl_xor_sync(0xffffffff, s1, 1);
        s1 += __shfl_xor_sync(0xffffffff, s1, 2);
        l0 = l0 * f0 + s0;
        l1 = l1 * f1 + s1;
#pragma unroll
        for (int nt = 0; nt < 8; nt++) {
            O[nt][0] *= f0; O[nt][1] *= f0;
            O[nt][2] *= f1; O[nt][3] *= f1;
        }

        // ---- O += P V (P from registers; no smem round-trip, no barrier) ----
#pragma unroll
        for (int j = 0; j < 4; j++) {
#pragma unroll
            for (int g = 0; g < 4; g++) {
                uint32_t vbh[4], vbl[4];
                ldm4(vbh, stb + 4608 * 4 + bof + g * (16 * 144) + j * 32);
                ldm4(vbl, stb + 6912 * 4 + bof + g * (16 * 144) + j * 32);
#pragma unroll
                for (int t = 0; t < 2; t++) {
                    const int nt = 2 * g + t;
                    mma16(O[nt], pfh[j], &vbl[2 * t]);
                    mma16(O[nt], pfl[j], &vbh[2 * t]);
                    mma16(O[nt], pfh[j], &vbh[2 * t]);
                }
            }
        }
    }

    // ---- epilogue: O /= l, write attention-out planes ----
    const float il0 = 1.0f / l0, il1 = 1.0f / l1;
    const size_t r0g = (size_t)(tokb + m0 + w * 16 + qr) * CCP + hq + kp;
    const size_t r1g = r0g + (size_t)8 * CCP;
#pragma unroll
    for (int nt = 0; nt < 8; nt++) {
        uint32_t hh, ll;
        split2(O[nt][0] * il0, O[nt][1] * il0, hh, ll);
        aoh[r0g + nt * 4] = hh; aol[r0g + nt * 4] = ll;
        split2(O[nt][2] * il1, O[nt][3] * il1, hh, ll);
        aoh[r1g + nt * 4] = hh; aol[r1g + nt * 4] = ll;
    }
}

// ---------------- unified tensor-core GEMM (bf16x3, cp.async 3-stage) ---------
// out[m,n] = sum_k A[m,k] * B[n,k]   (planes pre-split, pairs packed along k).
// Tile: 128(M) x 64(N) x 16(K), 8 warps (4x2), warp tile 32x32.
// MODE: 0 +bias | 1 gelu(+bias) | 2 +bias+add1 | 3 +bias+add1-add2
// VOUT: tiles with n0 >= 2*CC write V^T planes (token-paired) instead.
template<int MODE, bool OUTP, bool VOUT>
__global__ void __launch_bounds__(256, 3) mma_gemm(
    const uint32_t* __restrict__ Agh, const uint32_t* __restrict__ Agl,
    const uint32_t* __restrict__ Bgh, const uint32_t* __restrict__ Bgl,
    const float* __restrict__ bias,
    float* __restrict__ outF, uint32_t* __restrict__ outH, uint32_t* __restrict__ outL,
    uint32_t* __restrict__ vth, uint32_t* __restrict__ vtl,
    int K, int ldaP, int ldbP, int ldc,
    const float* __restrict__ add1, const float* __restrict__ add2)
{
    extern __shared__ __align__(16) uint32_t dsm[];
    constexpr uint32_t STB     = 18432;      // bytes/stage
    constexpr uint32_t OFF_AL  = 6144;
    constexpr uint32_t OFF_BH  = 12288;
    constexpr uint32_t OFF_BL  = 15360;

    const int tid  = threadIdx.x;
    const int lane = tid & 31;
    const int wid  = tid >> 5;
    const int wm   = wid >> 1;
    const int wn   = wid & 1;
    const int m0   = blockIdx.y * 128;
    const int n0   = blockIdx.x * 64;

    const int nsteps = K >> 4;

    const int arow = tid >> 1;
    const int akq  = (tid & 1) << 2;

    const uint32_t smb = smem_u32(dsm);
    const uint32_t aoff = (uint32_t)(wm * 32 + (lane & 15)) * 48 + (uint32_t)(lane >> 4) * 16;
    const uint32_t boff = (uint32_t)(wn * 32 + ((lane >> 4) & 1) * 8 + (lane & 7)) * 48 +
                          (uint32_t)((lane >> 3) & 1) * 16;

    auto issue = [&](int s, int st) {
        const uint32_t stb = smb + (uint32_t)st * STB;
        const size_t aog = (size_t)(m0 + arow) * ldaP + (s << 3) + akq;
        const uint32_t adst = stb + (uint32_t)arow * 48 + (uint32_t)akq * 4;
        cp16(adst, Agh + aog);
        cp16(adst + OFF_AL, Agl + aog);
        if (tid < 128) {
            const int br = tid >> 1;
            const size_t bog = (size_t)(n0 + br) * ldbP + (s << 3) + akq;
            const uint32_t bdst = stb + OFF_BH + (uint32_t)br * 48 + (uint32_t)akq * 4;
            cp16(bdst, Bgh + bog);
            cp16(bdst + (OFF_BL - OFF_BH), Bgl + bog);
        }
    };

    // prologue: stages 0,1
    issue(0, 0); CP_COMMIT();
    if (1 < nsteps) issue(1, 1);
    CP_COMMIT();

    float acc[2][4][4];
#pragma unroll
    for (int i = 0; i < 2; i++)
#pragma unroll
        for (int j = 0; j < 4; j++)
#pragma unroll
            for (int e = 0; e < 4; e++) acc[i][j][e] = 0.0f;

    const int kp = lane & 3;
    const int qr = lane >> 2;

    int st = 0, stn = 2;          // current stage, next-issue stage (mod 3)
    for (int s = 0; s < nsteps; s++) {
        CP_WAIT1();
        __syncthreads();
        if (s + 2 < nsteps) issue(s + 2, stn);
        CP_COMMIT();

        const uint32_t stb = smb + (uint32_t)st * STB;
        uint32_t ah[2][4], al4[2][4];
#pragma unroll
        for (int mt = 0; mt < 2; mt++) {
            const uint32_t ao = aoff + (uint32_t)mt * 768;
            ldm4(ah[mt],  stb + ao);
            ldm4(al4[mt], stb + OFF_AL + ao);
        }
        uint32_t bfh[2][4], bfl[2][4];
#pragma unroll
        for (int ntp = 0; ntp < 2; ntp++) {
            const uint32_t bo = boff + (uint32_t)ntp * 768;
            ldm4(bfh[ntp], stb + OFF_BH + bo);
            ldm4(bfl[ntp], stb + OFF_BL + bo);
        }
#pragma unroll
        for (int mt = 0; mt < 2; mt++)
#pragma unroll
            for (int ntp = 0; ntp < 2; ntp++)
#pragma unroll
                for (int j = 0; j < 2; j++) {
                    const int nt = 2 * ntp + j;
                    mma16(acc[mt][nt], ah[mt],  &bfl[ntp][2 * j]);
                    mma16(acc[mt][nt], al4[mt], &bfh[ntp][2 * j]);
                    mma16(acc[mt][nt], ah[mt],  &bfh[ntp][2 * j]);
                }

        st = (st == 2) ? 0 : st + 1;
        stn = (stn == 2) ? 0 : stn + 1;
    }

    // ---- epilogue ------------------------------------------------------------
    const bool vtile = VOUT && (n0 >= 2 * CC);
#pragma unroll
    for (int mt = 0; mt < 2; mt++) {
#pragma unroll
        for (int nt = 0; nt < 4; nt++) {
            const int r = m0 + wm * 32 + mt * 16 + qr;
            const int c = n0 + wn * 32 + nt * 8 + 2 * kp;
            float vv[4];
#pragma unroll
            for (int e = 0; e < 4; e++) {
                const int cc = c + (e & 1);
                float v = acc[mt][nt][e];
                v += bias[cc];
                if (MODE == 1) v = 0.5f * v * (1.0f + erff(v * 0.70710678118654752f));
                vv[e] = v;
            }
            if (vtile) {
                // V^T planes: pairs along tokens via lane exchange (qr bit0)
                const float o0 = __shfl_xor_sync(0xffffffff, vv[0], 4);
                const float o1 = __shfl_xor_sync(0xffffffff, vv[1], 4);
                const float o2 = __shfl_xor_sync(0xffffffff, vv[2], 4);
                const float o3 = __shfl_xor_sync(0xffffffff, vv[3], 4);
                const int b = m0 >> 10;
                const int head = (n0 - 2 * CC) >> 6;
                const int t = r - (b << 10);
                const int d = c - n0;
                const size_t base = (size_t)(b * HH + head) * (DH * TTP) +
                                    (size_t)d * TTP;
                uint32_t hh, ll;
                if ((qr & 1) == 0) {
                    const int tp = t >> 1;
                    split2(vv[0], o0, hh, ll);
                    vth[base + tp] = hh;        vtl[base + tp] = ll;
                    split2(vv[1], o1, hh, ll);
                    vth[base + TTP + tp] = hh;  vtl[base + TTP + tp] = ll;
                } else {
                    const int tp = (t + 7) >> 1;      // even token t-1+8
                    split2(o2, vv[2], hh, ll);
                    vth[base + tp] = hh;        vtl[base + tp] = ll;
                    split2(o3, vv[3], hh, ll);
                    vth[base + TTP + tp] = hh;  vtl[base + TTP + tp] = ll;
                }
            } else if (OUTP) {
                const int cp = c >> 1;
                uint32_t h0, l0, h1, l1;
                split2(vv[0], vv[1], h0, l0);
                split2(vv[2], vv[3], h1, l1);
                outH[(size_t)r * ldc + cp] = h0;
                outL[(size_t)r * ldc + cp] = l0;
                outH[(size_t)(r + 8) * ldc + cp] = h1;
                outL[(size_t)(r + 8) * ldc + cp] = l1;
            } else {
#pragma unroll
                for (int e = 0; e < 4; e++) {
                    const int rr = r + (e >> 1) * 8;
                    const int cc = c + (e & 1);
                    const size_t oidx = (size_t)rr * ldc + cc;
                    float v = vv[e];
                    if (MODE == 2) v += add1[oidx];
                    if (MODE == 3) v += add1[oidx] - add2[oidx];
                    outF[oidx] = v;
                }
            }
        }
    }
}

// ---------------- fused add + LayerNorm -> hi/lo planes -----------------------
__global__ void ln_kernel(const float* __restrict__ zin,
                          const float* __restrict__ u,
                          const float* __restrict__ emb,
                          const float* __restrict__ w,
                          const float* __restrict__ b,
                          uint32_t* __restrict__ oh,
                          uint32_t* __restrict__ ol) {
    __shared__ float red[256];
    const int row = blockIdx.x;
    const int tid = threadIdx.x;
    const size_t base = (size_t)row * CC;
    const float2* z2 = (const float2*)(zin + base);
    const float2* u2 = u ? (const float2*)(u + base) : nullptr;
    const float2* e2 = emb ? (const float2*)emb : nullptr;

    float2 va = z2[tid];
    float2 vb = make_float2(0.f, 0.f);
    if (u2) { float2 t = u2[tid]; va.x += t.x; va.y += t.y; }
    if (e2) { float2 t = e2[tid]; va.x += 0.1f * t.x; va.y += 0.1f * t.y; }
    if (tid < 128) {
        vb = z2[256 + tid];
        if (u2) { float2 t = u2[256 + tid]; vb.x += t.x; vb.y += t.y; }
        if (e2) { float2 t = e2[256 + tid]; vb.x += 0.1f * t.x; vb.y += 0.1f * t.y; }
    }
    float s = va.x + va.y + vb.x + vb.y;
    red[tid] = s; __syncthreads();
    for (int st = 128; st > 0; st >>= 1) {
        if (tid < st) red[tid] += red[tid + st];
        __syncthreads();
    }
    const float mu = red[0] * (1.0f / CC);
    __syncthreads();
    va.x -= mu; va.y -= mu;
    float s2 = va.x * va.x + va.y * va.y;
    if (tid < 128) { vb.x -= mu; vb.y -= mu; s2 += vb.x * vb.x + vb.y * vb.y; }
    red[tid] = s2; __syncthreads();
    for (int st = 128; st > 0; st >>= 1) {
        if (tid < st) red[tid] += red[tid + st];
        __syncthreads();
    }
    const float rs = rsqrtf(red[0] * (1.0f / CC) + 1e-5f);

    const float2* w2 = (const float2*)w;
    const float2* b2 = (const float2*)b;
    {
        float2 wc = w2[tid], bc = b2[tid];
        float y0 = va.x * rs * wc.x + bc.x;
        float y1 = va.y * rs * wc.y + bc.y;
        uint32_t hv, lv;
        split2(y0, y1, hv, lv);
        oh[(size_t)row * CCP + tid] = hv;
        ol[(size_t)row * CCP + tid] = lv;
    }
    if (tid < 128) {
        float2 wc = w2[256 + tid], bc = b2[256 + tid];
        float y0 = vb.x * rs * wc.x + bc.x;
        float y1 = vb.y * rs * wc.y + bc.y;
        uint32_t hv, lv;
        split2(y0, y1, hv, lv);
        oh[(size_t)row * CCP + 256 + tid] = hv;
        ol[(size_t)row * CCP + 256 + tid] = lv;
    }
}

// ---------------- Anderson acceleration update (one block per token) ---------
__global__ void anderson_kernel(float* __restrict__ z,
                                const float* __restrict__ res,
                                float* __restrict__ fh, int it) {
    __shared__ float sh[14][256];
    __shared__ float alpha_sh[4];
    const int n = blockIdx.x, tid = threadIdx.x;
    const size_t base = (size_t)n * CC;
    const int K = it < 4 ? it : 4;
    const int c0 = tid, c1 = tid + 256, c2 = tid + 512;

    float r0 = res[base + c0], r1 = res[base + c1], r2 = res[base + c2];
    float dF[4][3];
    for (int j = 0; j < K; j++) {
        const int slot = (it - K + j) & 3;
        const float* f = fh + (size_t)slot * ZSZ + base;
        dF[j][0] = f[c0] - r0; dF[j][1] = f[c1] - r1; dF[j][2] = f[c2] - r2;
    }

    if (K > 0) {
        int idx = 0;
        for (int k = 0; k < K; k++)
            for (int l = k; l < K; l++) {
                sh[idx][tid] = dF[k][0] * dF[l][0] + dF[k][1] * dF[l][1] + dF[k][2] * dF[l][2];
                idx++;
            }
        for (int k = 0; k < K; k++) {
            sh[idx][tid] = dF[k][0] * r0 + dF[k][1] * r1 + dF[k][2] * r2;
            idx++;
        }
        const int np = idx;
        __syncthreads();
        for (int st = 128; st > 0; st >>= 1) {
            if (tid < st)
                for (int v = 0; v < np; v++) sh[v][tid] += sh[v][tid + st];
            __syncthreads();
        }
        if (tid == 0) {
            float G[4][4], bv[4], al[4];
            int id2 = 0;
            for (int k = 0; k < K; k++)
                for (int l = k; l < K; l++) { G[k][l] = G[l][k] = sh[id2][0]; id2++; }
            for (int k = 0; k < K; k++) { G[k][k] += 1e-6f; bv[k] = sh[id2][0]; id2++; }
            for (int p = 0; p < K; p++) {
                const float inv = 1.0f / G[p][p];
                for (int rr = p + 1; rr < K; rr++) {
                    const float f2 = G[rr][p] * inv;
                    for (int cc = p; cc < K; cc++) G[rr][cc] -= f2 * G[p][cc];
                    bv[rr] -= f2 * bv[p];
                }
            }
            for (int p = K - 1; p >= 0; p--) {
                float s = bv[p];
                for (int cc = p + 1; cc < K; cc++) s -= G[p][cc] * al[cc];
                al[p] = s / G[p][p];
            }
            for (int k = 0; k < K; k++) alpha_sh[k] = al[k];
        }
        __syncthreads();
        float d0 = r0, d1 = r1, d2 = r2;
        for (int j = 0; j < K; j++) {
            const float a = alpha_sh[j];
            d0 -= a * dF[j][0]; d1 -= a * dF[j][1]; d2 -= a * dF[j][2];
        }
        z[base + c0] += d0; z[base + c1] += d1; z[base + c2] += d2;
    } else {
        z[base + c0] += r0; z[base + c1] += r1; z[base + c2] += r2;
    }

    float* fs = fh + (size_t)(it & 3) * ZSZ + base;
    fs[c0] = r0; fs[c1] = r1; fs[c2] = r2;
}

// ---------------- host launcher ----------------------------------------------
template <typename T>
static T* symaddr(const void* s) {
    void* p = nullptr;
    cudaGetSymbolAddress(&p, s);
    return (T*)p;
}

#define GEMM_SMEM  55296
#define FLASH_SMEM 73728

extern "C" void kernel_launch(void* const* d_in, const int* in_sizes, int n_in,
                              void* d_out, int out_size) {
    const float* u          = (const float*)d_in[0];
    const float* iter_emb   = (const float*)d_in[1];
    const float* ln1_w      = (const float*)d_in[2];
    const float* ln1_b      = (const float*)d_in[3];
    const float* in_proj_w  = (const float*)d_in[4];
    const float* in_proj_b  = (const float*)d_in[5];
    const float* out_proj_w = (const float*)d_in[6];
    const float* out_proj_b = (const float*)d_in[7];
    const float* ln2_w      = (const float*)d_in[8];
    const float* ln2_b      = (const float*)d_in[9];
    const float* mlp_w1     = (const float*)d_in[10];
    const float* mlp_b1     = (const float*)d_in[11];
    const float* mlp_w2     = (const float*)d_in[12];
    const float* mlp_b2     = (const float*)d_in[13];
    // d_in[14] = num_iters (fixed to 6 by setup_inputs)

    float* zp   = symaddr<float>(g_z);
    float* zap  = symaddr<float>(g_zattn);
    float* resp = symaddr<float>(g_res);
    float* fhp  = symaddr<float>(g_fhist);
    uint32_t* xh   = symaddr<uint32_t>(g_x_h);    uint32_t* xl   = symaddr<uint32_t>(g_x_l);
    uint32_t* qh   = symaddr<uint32_t>(g_qkv_h);  uint32_t* ql   = symaddr<uint32_t>(g_qkv_l);
    uint32_t* vth  = symaddr<uint32_t>(g_vt_h);   uint32_t* vtl  = symaddr<uint32_t>(g_vt_l);
    uint32_t* aoh  = symaddr<uint32_t>(g_ao_h);   uint32_t* aol  = symaddr<uint32_t>(g_ao_l);
    uint32_t* mih  = symaddr<uint32_t>(g_mid_h);  uint32_t* mil  = symaddr<uint32_t>(g_mid_l);
    uint32_t* wqh  = symaddr<uint32_t>(g_wqkv_h); uint32_t* wql  = symaddr<uint32_t>(g_wqkv_l);
    uint32_t* woh  = symaddr<uint32_t>(g_wo_h);   uint32_t* wol  = symaddr<uint32_t>(g_wo_l);
    uint32_t* w1h  = symaddr<uint32_t>(g_w1_h);   uint32_t* w1l  = symaddr<uint32_t>(g_w1_l);
    uint32_t* w2h  = symaddr<uint32_t>(g_w2_h);   uint32_t* w2l  = symaddr<uint32_t>(g_w2_l);

    cudaFuncSetAttribute((const void*)mma_gemm<0, true,  true >, cudaFuncAttributeMaxDynamicSharedMemorySize, GEMM_SMEM);
    cudaFuncSetAttribute((const void*)mma_gemm<2, false, false>, cudaFuncAttributeMaxDynamicSharedMemorySize, GEMM_SMEM);
    cudaFuncSetAttribute((const void*)mma_gemm<1, true,  false>, cudaFuncAttributeMaxDynamicSharedMemorySize, GEMM_SMEM);
    cudaFuncSetAttribute((const void*)mma_gemm<3, false, false>, cudaFuncAttributeMaxDynamicSharedMemorySize, GEMM_SMEM);
    cudaFuncSetAttribute((const void*)flash_attn, cudaFuncAttributeMaxDynamicSharedMemorySize, FLASH_SMEM);

    cudaMemsetAsync(zp, 0, (size_t)ZSZ * sizeof(float), 0);

    // split weights once per launch
    conv_kernel<<<(C3 * CCP + 255) / 256, 256>>>(in_proj_w,  wqh, wql, C3 * CCP);
    conv_kernel<<<(CC * CCP + 255) / 256, 256>>>(out_proj_w, woh, wol, CC * CCP);
    conv_kernel<<<(C4 * CCP + 255) / 256, 256>>>(mlp_w1,     w1h, w1l, C4 * CCP);
    conv_kernel<<<(CC * C4P + 255) / 256, 256>>>(mlp_w2,     w2h, w2l, CC * C4P);

    for (int it = 0; it < NUM_ITERS; it++) {
        // x = LN1(z + 0.1*emb[it] + u) -> planes
        ln_kernel<<<BT, 256>>>(zp, u, iter_emb + it * CC, ln1_w, ln1_b, xh, xl);

        // qkv = x @ Wqkv^T + b -> Q/K planes; V tiles write V^T planes directly
        mma_gemm<0, true, true><<<dim3(C3 / 64, BT / 128), 256, GEMM_SMEM>>>(
            xh, xl, wqh, wql, in_proj_b, nullptr, qh, ql, vth, vtl,
            CC, CCP, CCP, C3P, nullptr, nullptr);

        // fused attention: softmax(QK^T/8) @ V  -> planes
        flash_attn<<<dim3(TT / 128, BB * HH), 256, FLASH_SMEM>>>(qh, ql, vth, vtl, aoh, aol);

        // z_attn = z + attnout @ Wo^T + bo  (fp32)
        mma_gemm<2, false, false><<<dim3(CC / 64, BT / 128), 256, GEMM_SMEM>>>(
            aoh, aol, woh, wol, out_proj_b, zap, nullptr, nullptr, nullptr, nullptr,
            CC, CCP, CCP, CC, zp, nullptr);

        // h = LN2(z_attn) -> planes
        ln_kernel<<<BT, 256>>>(zap, nullptr, nullptr, ln2_w, ln2_b, xh, xl);

        // mid = gelu(h @ W1^T + b1) -> planes
        mma_gemm<1, true, false><<<dim3(C4 / 64, BT / 128), 256, GEMM_SMEM>>>(
            xh, xl, w1h, w1l, mlp_b1, nullptr, mih, mil, nullptr, nullptr,
            CC, CCP, CCP, C4P, nullptr, nullptr);

        // res = (mid @ W2^T + b2) + z_attn - z  (fp32)
        mma_gemm<3, false, false><<<dim3(CC / 64, BT / 128), 256, GEMM_SMEM>>>(
            mih, mil, w2h, w2l, mlp_b2, resp, nullptr, nullptr, nullptr, nullptr,
            C4, C4P, C4P, CC, zap, zp);

        // Anderson update of z, residual history push
        anderson_kernel<<<BT, 256>>>(zp, resp, fhp, it);
    }

    cudaMemcpyAsync(d_out, zp, (size_t)ZSZ * sizeof(float),
                    cudaMemcpyDeviceToDevice, 0);
}

// round 17
// speedup vs baseline: 1.0436x; 1.0072x over previous
#include <cuda_runtime.h>
#include <cuda_bf16.h>
#include <math.h>
#include <stdint.h>

// Problem constants (fixed by setup_inputs)
#define BB    4
#define TT    1024
#define CC    768
#define HH    12
#define DH    64
#define BT    4096            // B*T
#define C3    2304            // 3*C
#define C4    3072            // 4*C
#define ZSZ   3145728         // BT*C
#define NUM_ITERS 6
// pair (bf16x2) leading dims
#define CCP   384
#define C3P   1152
#define C4P   1536
#define TTP   512
#define DHP   32

#define LOG2E 1.4426950408889634f
#define SEXP  0.18033688011112042f    // 0.125 * log2(e)

// ---------------- scratch (device globals; no allocation allowed) -----------
__device__ float g_z[ZSZ];
__device__ float g_zattn[ZSZ];
__device__ float g_res[ZSZ];
__device__ float g_fhist[4 * ZSZ];

// hi/lo bf16x2 planes (pairs packed along k)
__device__ uint32_t g_x_h[BT * CCP],    g_x_l[BT * CCP];
__device__ uint32_t g_qkv_h[BT * C3P],  g_qkv_l[BT * C3P];
__device__ uint32_t g_vt_h[BB * HH * DH * TTP], g_vt_l[BB * HH * DH * TTP];
__device__ uint32_t g_ao_h[BT * CCP],   g_ao_l[BT * CCP];
__device__ uint32_t g_mid_h[BT * C4P],  g_mid_l[BT * C4P];
// weight planes (split once per launch)
__device__ uint32_t g_wqkv_h[C3 * CCP], g_wqkv_l[C3 * CCP];
__device__ uint32_t g_wo_h[CC * CCP],   g_wo_l[CC * CCP];
__device__ uint32_t g_w1_h[C4 * CCP],   g_w1_l[C4 * CCP];
__device__ uint32_t g_w2_h[CC * C4P],   g_w2_l[CC * C4P];

// ---------------- helpers ------------------------------------------------------
__device__ __forceinline__ void split2(float x, float y, uint32_t& hi, uint32_t& lo) {
    __nv_bfloat162 h2 = __floats2bfloat162_rn(x, y);
    float lx = x - __low2float(h2);
    float ly = y - __high2float(h2);
    __nv_bfloat162 l2 = __floats2bfloat162_rn(lx, ly);
    hi = *reinterpret_cast<uint32_t*>(&h2);
    lo = *reinterpret_cast<uint32_t*>(&l2);
}

__device__ __forceinline__ void mma16(float c[4], const uint32_t a[4], const uint32_t b[2]) {
    asm volatile(
        "mma.sync.aligned.m16n8k16.row.col.f32.bf16.bf16.f32 "
        "{%0,%1,%2,%3}, {%4,%5,%6,%7}, {%8,%9}, {%0,%1,%2,%3};\n"
        : "+f"(c[0]), "+f"(c[1]), "+f"(c[2]), "+f"(c[3])
        : "r"(a[0]), "r"(a[1]), "r"(a[2]), "r"(a[3]), "r"(b[0]), "r"(b[1]));
}

__device__ __forceinline__ void ldm4(uint32_t r[4], uint32_t addr) {
    asm volatile("ldmatrix.sync.aligned.m8n8.x4.shared.b16 {%0,%1,%2,%3}, [%4];"
        : "=r"(r[0]), "=r"(r[1]), "=r"(r[2]), "=r"(r[3]) : "r"(addr));
}

__device__ __forceinline__ uint32_t smem_u32(const void* p) {
    return (uint32_t)__cvta_generic_to_shared(p);
}

__device__ __forceinline__ void cp16(uint32_t dst, const uint32_t* src) {
    asm volatile("cp.async.cg.shared.global [%0], [%1], 16;" :: "r"(dst), "l"(src));
}
#define CP_COMMIT() asm volatile("cp.async.commit_group;" ::: "memory")
#define CP_WAIT0()  asm volatile("cp.async.wait_group 0;" ::: "memory")
#define CP_WAIT1()  asm volatile("cp.async.wait_group 1;" ::: "memory")

__device__ __forceinline__ float warp_sum(float v) {
#pragma unroll
    for (int o = 16; o > 0; o >>= 1) v += __shfl_xor_sync(0xffffffff, v, o);
    return v;
}

// ---------------- weight/activation split kernel ------------------------------
__global__ void conv_kernel(const float* __restrict__ w,
                            uint32_t* __restrict__ h,
                            uint32_t* __restrict__ l, int npairs) {
    int i = blockIdx.x * 256 + threadIdx.x;
    if (i < npairs) {
        float2 x = ((const float2*)w)[i];
        uint32_t hv, lv;
        split2(x.x, x.y, hv, lv);
        h[i] = hv; l[i] = lv;
    }
}

// ---------------- flash attention (fused QK^T + softmax + AV) ------------------
// grid (TT/128, BB*HH), block 256 = 8 warps; warp w owns q-rows [w*16, w*16+16).
// K-loop: 16 tiles of 64 tokens; K and V^T streamed via cp.async (2 stages).
// P stays in registers; Q staged through the stage-1 K/V buffer.
// SMEM: 2 stages x 9216 words = 73728 B -> 2 CTAs/SM (launch_bounds(256,2)).
__global__ void __launch_bounds__(256, 2) flash_attn(
    const uint32_t* __restrict__ qh_g, const uint32_t* __restrict__ ql_g,
    const uint32_t* __restrict__ vth,  const uint32_t* __restrict__ vtl,
    uint32_t* __restrict__ aoh, uint32_t* __restrict__ aol)
{
    extern __shared__ __align__(16) uint32_t dsm[];
    const int tid = threadIdx.x, lane = tid & 31, w = tid >> 5;
    const int bh = blockIdx.y, b = bh / HH, h = bh % HH;
    const int m0 = blockIdx.x * 128;
    const long tokb = (long)b * TT;
    const int hq = h * DHP;
    const int hk = CCP + h * DHP;
    const size_t vtb = (size_t)bh * DH * TTP;
    const uint32_t smb = smem_u32(dsm);
    const int qr = lane >> 2, kp = lane & 3;

    // ---- stage Q into stage-1 region, load register fragments ----
    for (int i = 0; i < 4; i++) {
        const int idx = tid + i * 256;            // 0..1023
        const int row = idx >> 3, ch = idx & 7;
        const size_t src = (size_t)(tokb + m0 + row) * C3P + hq + ch * 4;
        *(uint4*)&dsm[9216 + row * 36 + ch * 4]        = *(const uint4*)(qh_g + src);
        *(uint4*)&dsm[9216 + 4608 + row * 36 + ch * 4] = *(const uint4*)(ql_g + src);
    }
    __syncthreads();
    uint32_t qfh[4][4], qfl[4][4];
    {
        const uint32_t ao = smb + (uint32_t)(w * 16 + (lane & 15)) * 144 +
                            (uint32_t)(lane >> 4) * 16;
        for (int j = 0; j < 4; j++) {
            ldm4(qfh[j], ao + 9216 * 4 + j * 32);
            ldm4(qfl[j], ao + (9216 + 4608) * 4 + j * 32);
        }
    }
    __syncthreads();                               // all warps done reading Q smem

    // ---- K + V^T prefetch via cp.async ----
    auto issueK = [&](int kt) {
        const uint32_t stb = smb + (uint32_t)(kt & 1) * (9216 * 4);
        for (int i = 0; i < 2; i++) {
            const int idx = tid + i * 256;         // 0..511
            const int row = idx >> 3, ch = idx & 7;
            const size_t ksrc = (size_t)(tokb + kt * 64 + row) * C3P + hk + ch * 4;
            const uint32_t kdst = stb + (uint32_t)row * 144 + (uint32_t)ch * 16;
            cp16(kdst, qh_g + ksrc);
            cp16(kdst + 2304 * 4, ql_g + ksrc);
            const size_t vsrc = vtb + (size_t)row * TTP + kt * 32 + ch * 4;
            const uint32_t vdst = kdst + 4608 * 4;
            cp16(vdst, vth + vsrc);
            cp16(vdst + 2304 * 4, vtl + vsrc);
        }
        CP_COMMIT();
    };
    issueK(0);

    float O[8][4];
#pragma unroll
    for (int nt = 0; nt < 8; nt++)
#pragma unroll
        for (int e = 0; e < 4; e++) O[nt][e] = 0.0f;
    float m0r = -1e30f, m1r = -1e30f, l0 = 0.0f, l1 = 0.0f;

    const uint32_t bof = (uint32_t)(((lane >> 4) & 1) * 8 + (lane & 7)) * 144 +
                         (uint32_t)((lane >> 3) & 1) * 16;

    for (int kt = 0; kt < 16; kt++) {
        CP_WAIT0();
        __syncthreads();                           // K/V[kt] ready; all warps past kt-1
        if (kt + 1 < 16) issueK(kt + 1);

        // ---- S = Q K^T (raw, scale folded into exp) ----
        float sacc[8][4];
#pragma unroll
        for (int nt = 0; nt < 8; nt++)
#pragma unroll
            for (int e = 0; e < 4; e++) sacc[nt][e] = 0.0f;
        const uint32_t stb = smb + (uint32_t)(kt & 1) * (9216 * 4);
#pragma unroll
        for (int g = 0; g < 4; g++)
#pragma unroll
            for (int j = 0; j < 4; j++) {
                uint32_t kb[4], kl[4];
                ldm4(kb, stb + bof + g * (16 * 144) + j * 32);
                ldm4(kl, stb + 2304 * 4 + bof + g * (16 * 144) + j * 32);
#pragma unroll
                for (int t = 0; t < 2; t++) {
                    const int nt = 2 * g + t;
                    mma16(sacc[nt], qfh[j], &kl[2 * t]);
                    mma16(sacc[nt], qfl[j], &kb[2 * t]);
                    mma16(sacc[nt], qfh[j], &kb[2 * t]);
                }
            }

        // ---- online softmax -> P directly into A-fragment registers ----
        float tm0 = -1e30f, tm1 = -1e30f;
#pragma unroll
        for (int nt = 0; nt < 8; nt++) {
            tm0 = fmaxf(tm0, fmaxf(sacc[nt][0], sacc[nt][1]));
            tm1 = fmaxf(tm1, fmaxf(sacc[nt][2], sacc[nt][3]));
        }
        tm0 = fmaxf(tm0, __shfl_xor_sync(0xffffffff, tm0, 1));
        tm0 = fmaxf(tm0, __shfl_xor_sync(0xffffffff, tm0, 2));
        tm1 = fmaxf(tm1, __shfl_xor_sync(0xffffffff, tm1, 1));
        tm1 = fmaxf(tm1, __shfl_xor_sync(0xffffffff, tm1, 2));
        const float mn0 = fmaxf(m0r, tm0 * 0.125f);
        const float mn1 = fmaxf(m1r, tm1 * 0.125f);
        const float f0 = exp2f((m0r - mn0) * LOG2E);
        const float f1 = exp2f((m1r - mn1) * LOG2E);
        m0r = mn0; m1r = mn1;
        const float mm0 = mn0 * LOG2E, mm1 = mn1 * LOG2E;
        float s0 = 0.0f, s1 = 0.0f;
        uint32_t pfh[4][4], pfl[4][4];
#pragma unroll
        for (int nt = 0; nt < 8; nt++) {
            const float p0 = exp2f(fmaf(sacc[nt][0], SEXP, -mm0));
            const float p1 = exp2f(fmaf(sacc[nt][1], SEXP, -mm0));
            const float p2 = exp2f(fmaf(sacc[nt][2], SEXP, -mm1));
            const float p3 = exp2f(fmaf(sacc[nt][3], SEXP, -mm1));
            s0 += p0 + p1; s1 += p2 + p3;
            const int j = nt >> 1;
            if ((nt & 1) == 0) {
                split2(p0, p1, pfh[j][0], pfl[j][0]);
                split2(p2, p3, pfh[j][1], pfl[j][1]);
            } else {
                split2(p0, p1, pfh[j][2], pfl[j][2]);
                split2(p2, p3, pfh[j][3], pfl[j][3]);
            }
        }
        s0 += __shfl_xor_sync(0xffffffff, s0, 1);
        s0 += __shfl_xor_sync(0xffffffff, s0, 2);
        s1 += __shfl_xor_sync(0xffffffff, s1, 1);
        s1 += __shfl_xor_sync(0xffffffff, s1, 2);
        l0 = l0 * f0 + s0;
        l1 = l1 * f1 + s1;
#pragma unroll
        for (int nt = 0; nt < 8; nt++) {
            O[nt][0] *= f0; O[nt][1] *= f0;
            O[nt][2] *= f1; O[nt][3] *= f1;
        }

        // ---- O += P V (P from registers) ----
#pragma unroll
        for (int j = 0; j < 4; j++) {
#pragma unroll
            for (int g = 0; g < 4; g++) {
                uint32_t vbh[4], vbl[4];
                ldm4(vbh, stb + 4608 * 4 + bof + g * (16 * 144) + j * 32);
                ldm4(vbl, stb + 6912 * 4 + bof + g * (16 * 144) + j * 32);
#pragma unroll
                for (int t = 0; t < 2; t++) {
                    const int nt = 2 * g + t;
                    mma16(O[nt], pfh[j], &vbl[2 * t]);
                    mma16(O[nt], pfl[j], &vbh[2 * t]);
                    mma16(O[nt], pfh[j], &vbh[2 * t]);
                }
            }
        }
    }

    // ---- epilogue: O /= l, write attention-out planes ----
    const float il0 = 1.0f / l0, il1 = 1.0f / l1;
    const size_t r0g = (size_t)(tokb + m0 + w * 16 + qr) * CCP + hq + kp;
    const size_t r1g = r0g + (size_t)8 * CCP;
#pragma unroll
    for (int nt = 0; nt < 8; nt++) {
        uint32_t hh, ll;
        split2(O[nt][0] * il0, O[nt][1] * il0, hh, ll);
        aoh[r0g + nt * 4] = hh; aol[r0g + nt * 4] = ll;
        split2(O[nt][2] * il1, O[nt][3] * il1, hh, ll);
        aoh[r1g + nt * 4] = hh; aol[r1g + nt * 4] = ll;
    }
}

// ---------------- unified tensor-core GEMM (bf16x3, cp.async 3-stage) ---------
// out[m,n] = sum_k A[m,k] * B[n,k]   (planes pre-split, pairs packed along k).
// Tile: 128(M) x 64(N) x 16(K), 8 warps (4x2), warp tile 32x32.
// MODE: 0 +bias | 1 gelu(+bias) | 2 +bias+add1 | 3 +bias+add1-add2
// VOUT: tiles with n0 >= 2*CC write V^T planes (token-paired) instead.
template<int MODE, bool OUTP, bool VOUT>
__global__ void __launch_bounds__(256, 3) mma_gemm(
    const uint32_t* __restrict__ Agh, const uint32_t* __restrict__ Agl,
    const uint32_t* __restrict__ Bgh, const uint32_t* __restrict__ Bgl,
    const float* __restrict__ bias,
    float* __restrict__ outF, uint32_t* __restrict__ outH, uint32_t* __restrict__ outL,
    uint32_t* __restrict__ vth, uint32_t* __restrict__ vtl,
    int K, int ldaP, int ldbP, int ldc,
    const float* __restrict__ add1, const float* __restrict__ add2)
{
    extern __shared__ __align__(16) uint32_t dsm[];
    constexpr uint32_t STB     = 18432;      // bytes/stage
    constexpr uint32_t OFF_AL  = 6144;
    constexpr uint32_t OFF_BH  = 12288;
    constexpr uint32_t OFF_BL  = 15360;

    const int tid  = threadIdx.x;
    const int lane = tid & 31;
    const int wid  = tid >> 5;
    const int wm   = wid >> 1;
    const int wn   = wid & 1;
    const int m0   = blockIdx.y * 128;
    const int n0   = blockIdx.x * 64;

    const int nsteps = K >> 4;

    const int arow = tid >> 1;
    const int akq  = (tid & 1) << 2;

    const uint32_t smb = smem_u32(dsm);
    const uint32_t aoff = (uint32_t)(wm * 32 + (lane & 15)) * 48 + (uint32_t)(lane >> 4) * 16;
    const uint32_t boff = (uint32_t)(wn * 32 + ((lane >> 4) & 1) * 8 + (lane & 7)) * 48 +
                          (uint32_t)((lane >> 3) & 1) * 16;

    auto issue = [&](int s, int st) {
        const uint32_t stb = smb + (uint32_t)st * STB;
        const size_t aog = (size_t)(m0 + arow) * ldaP + (s << 3) + akq;
        const uint32_t adst = stb + (uint32_t)arow * 48 + (uint32_t)akq * 4;
        cp16(adst, Agh + aog);
        cp16(adst + OFF_AL, Agl + aog);
        if (tid < 128) {
            const int br = tid >> 1;
            const size_t bog = (size_t)(n0 + br) * ldbP + (s << 3) + akq;
            const uint32_t bdst = stb + OFF_BH + (uint32_t)br * 48 + (uint32_t)akq * 4;
            cp16(bdst, Bgh + bog);
            cp16(bdst + (OFF_BL - OFF_BH), Bgl + bog);
        }
    };

    // prologue: stages 0,1
    issue(0, 0); CP_COMMIT();
    if (1 < nsteps) issue(1, 1);
    CP_COMMIT();

    float acc[2][4][4];
#pragma unroll
    for (int i = 0; i < 2; i++)
#pragma unroll
        for (int j = 0; j < 4; j++)
#pragma unroll
            for (int e = 0; e < 4; e++) acc[i][j][e] = 0.0f;

    const int kp = lane & 3;
    const int qr = lane >> 2;

    int st = 0, stn = 2;          // current stage, next-issue stage (mod 3)
    for (int s = 0; s < nsteps; s++) {
        CP_WAIT1();
        __syncthreads();
        if (s + 2 < nsteps) issue(s + 2, stn);
        CP_COMMIT();

        const uint32_t stb = smb + (uint32_t)st * STB;
        uint32_t ah[2][4], al4[2][4];
#pragma unroll
        for (int mt = 0; mt < 2; mt++) {
            const uint32_t ao = aoff + (uint32_t)mt * 768;
            ldm4(ah[mt],  stb + ao);
            ldm4(al4[mt], stb + OFF_AL + ao);
        }
        uint32_t bfh[2][4], bfl[2][4];
#pragma unroll
        for (int ntp = 0; ntp < 2; ntp++) {
            const uint32_t bo = boff + (uint32_t)ntp * 768;
            ldm4(bfh[ntp], stb + OFF_BH + bo);
            ldm4(bfl[ntp], stb + OFF_BL + bo);
        }
#pragma unroll
        for (int mt = 0; mt < 2; mt++)
#pragma unroll
            for (int ntp = 0; ntp < 2; ntp++)
#pragma unroll
                for (int j = 0; j < 2; j++) {
                    const int nt = 2 * ntp + j;
                    mma16(acc[mt][nt], ah[mt],  &bfl[ntp][2 * j]);
                    mma16(acc[mt][nt], al4[mt], &bfh[ntp][2 * j]);
                    mma16(acc[mt][nt], ah[mt],  &bfh[ntp][2 * j]);
                }

        st = (st == 2) ? 0 : st + 1;
        stn = (stn == 2) ? 0 : stn + 1;
    }

    // ---- epilogue ------------------------------------------------------------
    const bool vtile = VOUT && (n0 >= 2 * CC);
#pragma unroll
    for (int mt = 0; mt < 2; mt++) {
#pragma unroll
        for (int nt = 0; nt < 4; nt++) {
            const int r = m0 + wm * 32 + mt * 16 + qr;
            const int c = n0 + wn * 32 + nt * 8 + 2 * kp;
            float vv[4];
#pragma unroll
            for (int e = 0; e < 4; e++) {
                const int cc = c + (e & 1);
                float v = acc[mt][nt][e];
                v += bias[cc];
                if (MODE == 1) v = 0.5f * v * (1.0f + erff(v * 0.70710678118654752f));
                vv[e] = v;
            }
            if (vtile) {
                const float o0 = __shfl_xor_sync(0xffffffff, vv[0], 4);
                const float o1 = __shfl_xor_sync(0xffffffff, vv[1], 4);
                const float o2 = __shfl_xor_sync(0xffffffff, vv[2], 4);
                const float o3 = __shfl_xor_sync(0xffffffff, vv[3], 4);
                const int b = m0 >> 10;
                const int head = (n0 - 2 * CC) >> 6;
                const int t = r - (b << 10);
                const int d = c - n0;
                const size_t base = (size_t)(b * HH + head) * (DH * TTP) +
                                    (size_t)d * TTP;
                uint32_t hh, ll;
                if ((qr & 1) == 0) {
                    const int tp = t >> 1;
                    split2(vv[0], o0, hh, ll);
                    vth[base + tp] = hh;        vtl[base + tp] = ll;
                    split2(vv[1], o1, hh, ll);
                    vth[base + TTP + tp] = hh;  vtl[base + TTP + tp] = ll;
                } else {
                    const int tp = (t + 7) >> 1;
                    split2(o2, vv[2], hh, ll);
                    vth[base + tp] = hh;        vtl[base + tp] = ll;
                    split2(o3, vv[3], hh, ll);
                    vth[base + TTP + tp] = hh;  vtl[base + TTP + tp] = ll;
                }
            } else if (OUTP) {
                const int cp = c >> 1;
                uint32_t h0, l0, h1, l1;
                split2(vv[0], vv[1], h0, l0);
                split2(vv[2], vv[3], h1, l1);
                outH[(size_t)r * ldc + cp] = h0;
                outL[(size_t)r * ldc + cp] = l0;
                outH[(size_t)(r + 8) * ldc + cp] = h1;
                outL[(size_t)(r + 8) * ldc + cp] = l1;
            } else {
#pragma unroll
                for (int e = 0; e < 4; e++) {
                    const int rr = r + (e >> 1) * 8;
                    const int cc = c + (e & 1);
                    const size_t oidx = (size_t)rr * ldc + cc;
                    float v = vv[e];
                    if (MODE == 2) v += add1[oidx];
                    if (MODE == 3) v += add1[oidx] - add2[oidx];
                    outF[oidx] = v;
                }
            }
        }
    }
}

// ---------------- fused add + LayerNorm -> hi/lo planes -----------------------
// Shuffle-based reductions: 3 barriers instead of 16.
__global__ void ln_kernel(const float* __restrict__ zin,
                          const float* __restrict__ u,
                          const float* __restrict__ emb,
                          const float* __restrict__ w,
                          const float* __restrict__ b,
                          uint32_t* __restrict__ oh,
                          uint32_t* __restrict__ ol) {
    __shared__ float red[8];
    const int row = blockIdx.x;
    const int tid = threadIdx.x;
    const int lane = tid & 31, wp = tid >> 5;
    const size_t base = (size_t)row * CC;
    const float2* z2 = (const float2*)(zin + base);
    const float2* u2 = u ? (const float2*)(u + base) : nullptr;
    const float2* e2 = emb ? (const float2*)emb : nullptr;

    float2 va = z2[tid];
    float2 vb = make_float2(0.f, 0.f);
    if (u2) { float2 t = u2[tid]; va.x += t.x; va.y += t.y; }
    if (e2) { float2 t = e2[tid]; va.x += 0.1f * t.x; va.y += 0.1f * t.y; }
    if (tid < 128) {
        vb = z2[256 + tid];
        if (u2) { float2 t = u2[256 + tid]; vb.x += t.x; vb.y += t.y; }
        if (e2) { float2 t = e2[256 + tid]; vb.x += 0.1f * t.x; vb.y += 0.1f * t.y; }
    }
    float s = warp_sum(va.x + va.y + vb.x + vb.y);
    if (lane == 0) red[wp] = s;
    __syncthreads();
    float tot = 0.0f;
#pragma unroll
    for (int i = 0; i < 8; i++) tot += red[i];
    const float mu = tot * (1.0f / CC);

    va.x -= mu; va.y -= mu;
    float s2 = va.x * va.x + va.y * va.y;
    if (tid < 128) { vb.x -= mu; vb.y -= mu; s2 += vb.x * vb.x + vb.y * vb.y; }
    s2 = warp_sum(s2);
    __syncthreads();                   // all done reading red before overwrite
    if (lane == 0) red[wp] = s2;
    __syncthreads();
    float tot2 = 0.0f;
#pragma unroll
    for (int i = 0; i < 8; i++) tot2 += red[i];
    const float rs = rsqrtf(tot2 * (1.0f / CC) + 1e-5f);

    const float2* w2 = (const float2*)w;
    const float2* b2 = (const float2*)b;
    {
        float2 wc = w2[tid], bc = b2[tid];
        float y0 = va.x * rs * wc.x + bc.x;
        float y1 = va.y * rs * wc.y + bc.y;
        uint32_t hv, lv;
        split2(y0, y1, hv, lv);
        oh[(size_t)row * CCP + tid] = hv;
        ol[(size_t)row * CCP + tid] = lv;
    }
    if (tid < 128) {
        float2 wc = w2[256 + tid], bc = b2[256 + tid];
        float y0 = vb.x * rs * wc.x + bc.x;
        float y1 = vb.y * rs * wc.y + bc.y;
        uint32_t hv, lv;
        split2(y0, y1, hv, lv);
        oh[(size_t)row * CCP + 256 + tid] = hv;
        ol[(size_t)row * CCP + 256 + tid] = lv;
    }
}

// ---------------- Anderson acceleration update (one block per token) ---------
// Shuffle-based Gram reduction: 2 barriers instead of 9.
__global__ void anderson_kernel(float* __restrict__ z,
                                const float* __restrict__ res,
                                float* __restrict__ fh, int it) {
    __shared__ float part[14][8];
    __shared__ float alpha_sh[4];
    const int n = blockIdx.x, tid = threadIdx.x;
    const int lane = tid & 31, wp = tid >> 5;
    const size_t base = (size_t)n * CC;
    const int K = it < 4 ? it : 4;
    const int c0 = tid, c1 = tid + 256, c2 = tid + 512;

    float r0 = res[base + c0], r1 = res[base + c1], r2 = res[base + c2];
    float dF[4][3];
    for (int j = 0; j < K; j++) {
        const int slot = (it - K + j) & 3;
        const float* f = fh + (size_t)slot * ZSZ + base;
        dF[j][0] = f[c0] - r0; dF[j][1] = f[c1] - r1; dF[j][2] = f[c2] - r2;
    }

    if (K > 0) {
        float p[14];
        int idx = 0;
        for (int k = 0; k < K; k++)
            for (int l = k; l < K; l++) {
                p[idx++] = dF[k][0] * dF[l][0] + dF[k][1] * dF[l][1] + dF[k][2] * dF[l][2];
            }
        for (int k = 0; k < K; k++) {
            p[idx++] = dF[k][0] * r0 + dF[k][1] * r1 + dF[k][2] * r2;
        }
        const int np = idx;
        for (int v = 0; v < np; v++) p[v] = warp_sum(p[v]);
        if (lane == 0)
            for (int v = 0; v < np; v++) part[v][wp] = p[v];
        __syncthreads();
        if (tid == 0) {
            float G[4][4], bv[4], al[4];
            int id2 = 0;
            for (int k = 0; k < K; k++)
                for (int l = k; l < K; l++) {
                    float s = part[id2][0] + part[id2][1] + part[id2][2] + part[id2][3] +
                              part[id2][4] + part[id2][5] + part[id2][6] + part[id2][7];
                    G[k][l] = G[l][k] = s; id2++;
                }
            for (int k = 0; k < K; k++) {
                float s = part[id2][0] + part[id2][1] + part[id2][2] + part[id2][3] +
                          part[id2][4] + part[id2][5] + part[id2][6] + part[id2][7];
                G[k][k] += 0.0f;   // placeholder keeps structure clear
                bv[k] = s; id2++;
            }
            for (int k = 0; k < K; k++) G[k][k] += 1e-6f;
            for (int pp = 0; pp < K; pp++) {
                const float inv = 1.0f / G[pp][pp];
                for (int rr = pp + 1; rr < K; rr++) {
                    const float f2 = G[rr][pp] * inv;
                    for (int cc = pp; cc < K; cc++) G[rr][cc] -= f2 * G[pp][cc];
                    bv[rr] -= f2 * bv[pp];
                }
            }
            for (int pp = K - 1; pp >= 0; pp--) {
                float s = bv[pp];
                for (int cc = pp + 1; cc < K; cc++) s -= G[pp][cc] * al[cc];
                al[pp] = s / G[pp][pp];
            }
            for (int k = 0; k < K; k++) alpha_sh[k] = al[k];
        }
        __syncthreads();
        float d0 = r0, d1 = r1, d2 = r2;
        for (int j = 0; j < K; j++) {
            const float a = alpha_sh[j];
            d0 -= a * dF[j][0]; d1 -= a * dF[j][1]; d2 -= a * dF[j][2];
        }
        z[base + c0] += d0; z[base + c1] += d1; z[base + c2] += d2;
    } else {
        z[base + c0] += r0; z[base + c1] += r1; z[base + c2] += r2;
    }

    float* fs = fh + (size_t)(it & 3) * ZSZ + base;
    fs[c0] = r0; fs[c1] = r1; fs[c2] = r2;
}

// ---------------- host launcher ----------------------------------------------
template <typename T>
static T* symaddr(const void* s) {
    void* p = nullptr;
    cudaGetSymbolAddress(&p, s);
    return (T*)p;
}

#define GEMM_SMEM  55296
#define FLASH_SMEM 73728

extern "C" void kernel_launch(void* const* d_in, const int* in_sizes, int n_in,
                              void* d_out, int out_size) {
    const float* u          = (const float*)d_in[0];
    const float* iter_emb   = (const float*)d_in[1];
    const float* ln1_w      = (const float*)d_in[2];
    const float* ln1_b      = (const float*)d_in[3];
    const float* in_proj_w  = (const float*)d_in[4];
    const float* in_proj_b  = (const float*)d_in[5];
    const float* out_proj_w = (const float*)d_in[6];
    const float* out_proj_b = (const float*)d_in[7];
    const float* ln2_w      = (const float*)d_in[8];
    const float* ln2_b      = (const float*)d_in[9];
    const float* mlp_w1     = (const float*)d_in[10];
    const float* mlp_b1     = (const float*)d_in[11];
    const float* mlp_w2     = (const float*)d_in[12];
    const float* mlp_b2     = (const float*)d_in[13];
    // d_in[14] = num_iters (fixed to 6 by setup_inputs)

    float* zp   = symaddr<float>(g_z);
    float* zap  = symaddr<float>(g_zattn);
    float* resp = symaddr<float>(g_res);
    float* fhp  = symaddr<float>(g_fhist);
    uint32_t* xh   = symaddr<uint32_t>(g_x_h);    uint32_t* xl   = symaddr<uint32_t>(g_x_l);
    uint32_t* qh   = symaddr<uint32_t>(g_qkv_h);  uint32_t* ql   = symaddr<uint32_t>(g_qkv_l);
    uint32_t* vth  = symaddr<uint32_t>(g_vt_h);   uint32_t* vtl  = symaddr<uint32_t>(g_vt_l);
    uint32_t* aoh  = symaddr<uint32_t>(g_ao_h);   uint32_t* aol  = symaddr<uint32_t>(g_ao_l);
    uint32_t* mih  = symaddr<uint32_t>(g_mid_h);  uint32_t* mil  = symaddr<uint32_t>(g_mid_l);
    uint32_t* wqh  = symaddr<uint32_t>(g_wqkv_h); uint32_t* wql  = symaddr<uint32_t>(g_wqkv_l);
    uint32_t* woh  = symaddr<uint32_t>(g_wo_h);   uint32_t* wol  = symaddr<uint32_t>(g_wo_l);
    uint32_t* w1h  = symaddr<uint32_t>(g_w1_h);   uint32_t* w1l  = symaddr<uint32_t>(g_w1_l);
    uint32_t* w2h  = symaddr<uint32_t>(g_w2_h);   uint32_t* w2l  = symaddr<uint32_t>(g_w2_l);

    cudaFuncSetAttribute((const void*)mma_gemm<0, true,  true >, cudaFuncAttributeMaxDynamicSharedMemorySize, GEMM_SMEM);
    cudaFuncSetAttribute((const void*)mma_gemm<2, false, false>, cudaFuncAttributeMaxDynamicSharedMemorySize, GEMM_SMEM);
    cudaFuncSetAttribute((const void*)mma_gemm<1, true,  false>, cudaFuncAttributeMaxDynamicSharedMemorySize, GEMM_SMEM);
    cudaFuncSetAttribute((const void*)mma_gemm<3, false, false>, cudaFuncAttributeMaxDynamicSharedMemorySize, GEMM_SMEM);
    cudaFuncSetAttribute((const void*)flash_attn, cudaFuncAttributeMaxDynamicSharedMemorySize, FLASH_SMEM);

    cudaMemsetAsync(zp, 0, (size_t)ZSZ * sizeof(float), 0);

    // split weights once per launch
    conv_kernel<<<(C3 * CCP + 255) / 256, 256>>>(in_proj_w,  wqh, wql, C3 * CCP);
    conv_kernel<<<(CC * CCP + 255) / 256, 256>>>(out_proj_w, woh, wol, CC * CCP);
    conv_kernel<<<(C4 * CCP + 255) / 256, 256>>>(mlp_w1,     w1h, w1l, C4 * CCP);
    conv_kernel<<<(CC * C4P + 255) / 256, 256>>>(mlp_w2,     w2h, w2l, CC * C4P);

    for (int it = 0; it < NUM_ITERS; it++) {
        // x = LN1(z + 0.1*emb[it] + u) -> planes
        ln_kernel<<<BT, 256>>>(zp, u, iter_emb + it * CC, ln1_w, ln1_b, xh, xl);

        // qkv = x @ Wqkv^T + b -> Q/K planes; V tiles write V^T planes directly
        mma_gemm<0, true, true><<<dim3(C3 / 64, BT / 128), 256, GEMM_SMEM>>>(
            xh, xl, wqh, wql, in_proj_b, nullptr, qh, ql, vth, vtl,
            CC, CCP, CCP, C3P, nullptr, nullptr);

        // fused attention: softmax(QK^T/8) @ V  -> planes
        flash_attn<<<dim3(TT / 128, BB * HH), 256, FLASH_SMEM>>>(qh, ql, vth, vtl, aoh, aol);

        // z_attn = z + attnout @ Wo^T + bo  (fp32)
        mma_gemm<2, false, false><<<dim3(CC / 64, BT / 128), 256, GEMM_SMEM>>>(
            aoh, aol, woh, wol, out_proj_b, zap, nullptr, nullptr, nullptr, nullptr,
            CC, CCP, CCP, CC, zp, nullptr);

        // h = LN2(z_attn) -> planes
        ln_kernel<<<BT, 256>>>(zap, nullptr, nullptr, ln2_w, ln2_b, xh, xl);

        // mid = gelu(h @ W1^T + b1) -> planes
        mma_gemm<1, true, false><<<dim3(C4 / 64, BT / 128), 256, GEMM_SMEM>>>(
            xh, xl, w1h, w1l, mlp_b1, nullptr, mih, mil, nullptr, nullptr,
            CC, CCP, CCP, C4P, nullptr, nullptr);

        // res = (mid @ W2^T + b2) + z_attn - z  (fp32)
        mma_gemm<3, false, false><<<dim3(CC / 64, BT / 128), 256, GEMM_SMEM>>>(
            mih, mil, w2h, w2l, mlp_b2, resp, nullptr, nullptr, nullptr, nullptr,
            C4, C4P, C4P, CC, zap, zp);

        // Anderson update of z, residual history push
        anderson_kernel<<<BT, 256>>>(zp, resp, fhp, it);
    }

    cudaMemcpyAsync(d_out, zp, (size_t)ZSZ * sizeof(float),
                    cudaMemcpyDeviceToDevice, 0);
}